// round 5
// baseline (speedup 1.0000x reference)
#include <cuda_runtime.h>

typedef unsigned long long ull;

#define SEQ   2048
#define NB    2
#define CM    1024
#define NHEAD 16
#define HDIM  64
#define FF    4096
#define MTOT  (NB*SEQ)   // 4096 rows total

// ---------------- scratch (static device globals; no allocation) -------------
__device__ float g_qkv[(size_t)MTOT * 3 * CM];   // 50 MB
__device__ float g_attn[(size_t)MTOT * CM];      // 16 MB
__device__ float g_res[(size_t)MTOT * CM];       // 16 MB
__device__ float g_x[(size_t)MTOT * CM];         // 16 MB
__device__ float g_ff[(size_t)MTOT * FF];        // 64 MB

// ---------------- packed f32x2 helpers (FFMA2 path, PTX-only) ---------------
__device__ __forceinline__ ull pack2(float x, float y) {
    ull r;
    asm("mov.b64 %0, {%1, %2};" : "=l"(r) : "f"(x), "f"(y));
    return r;
}
__device__ __forceinline__ float2 unpack2(ull v) {
    float2 r;
    asm("mov.b64 {%0, %1}, %2;" : "=f"(r.x), "=f"(r.y) : "l"(v));
    return r;
}
__device__ __forceinline__ ull fma2(ull a, ull b, ull c) {
    ull d;
    asm("fma.rn.f32x2 %0, %1, %2, %3;" : "=l"(d) : "l"(a), "l"(b), "l"(c));
    return d;
}
__device__ __forceinline__ ull mul2(ull a, ull b) {
    ull d;
    asm("mul.rn.f32x2 %0, %1, %2;" : "=l"(d) : "l"(a), "l"(b));
    return d;
}

// =============================================================================
// GEMM: C[M,N] = A[M,K] * B[N,K]^T  (+bias, +relu, +residual)
// Tiles: BM=BN=128, BK=16, 256 threads, 8x8 per-thread microtile (f32x2 accs)
// M, N, K are all multiples of the tile sizes for this problem -> no bounds.
// =============================================================================
template <int RELU>
__global__ __launch_bounds__(256, 2)
void gemm_nt(const float* __restrict__ A, const float* __restrict__ Bm,
             const float* __restrict__ bias, const float* __restrict__ add,
             float* __restrict__ C, int M, int N, int K)
{
    __shared__ float As[16][128];
    __shared__ float Bs[16][128];

    const int tid = threadIdx.x;
    const int tx  = tid & 15;        // 0..15 -> n microtile
    const int ty  = tid >> 4;        // 0..15 -> m microtile
    const int m0  = blockIdx.y * 128;
    const int n0  = blockIdx.x * 128;

    // tile-load indices: 512 float4 per operand per slab, 2 per thread
    const int ra = tid >> 2;                // 0..63
    const int ca = (tid & 3) << 2;          // 0,4,8,12

    const float* aG  = A  + (size_t)(m0 + ra)      * K + ca;
    const float* aG2 = A  + (size_t)(m0 + ra + 64) * K + ca;
    const float* bG  = Bm + (size_t)(n0 + ra)      * K + ca;
    const float* bG2 = Bm + (size_t)(n0 + ra + 64) * K + ca;

    ull acc[8][4];
#pragma unroll
    for (int i = 0; i < 8; i++)
#pragma unroll
        for (int j = 0; j < 4; j++) acc[i][j] = 0ull;

    float4 av0 = *(const float4*)(aG);
    float4 av1 = *(const float4*)(aG2);
    float4 bv0 = *(const float4*)(bG);
    float4 bv1 = *(const float4*)(bG2);

    for (int k0 = 0; k0 < K; k0 += 16) {
        // stage slab into smem (transposed: [k][m] / [k][n])
        As[ca + 0][ra]      = av0.x; As[ca + 1][ra]      = av0.y;
        As[ca + 2][ra]      = av0.z; As[ca + 3][ra]      = av0.w;
        As[ca + 0][ra + 64] = av1.x; As[ca + 1][ra + 64] = av1.y;
        As[ca + 2][ra + 64] = av1.z; As[ca + 3][ra + 64] = av1.w;
        Bs[ca + 0][ra]      = bv0.x; Bs[ca + 1][ra]      = bv0.y;
        Bs[ca + 2][ra]      = bv0.z; Bs[ca + 3][ra]      = bv0.w;
        Bs[ca + 0][ra + 64] = bv1.x; Bs[ca + 1][ra + 64] = bv1.y;
        Bs[ca + 2][ra + 64] = bv1.z; Bs[ca + 3][ra + 64] = bv1.w;
        __syncthreads();

        if (k0 + 16 < K) {  // prefetch next slab (overlaps with compute)
            av0 = *(const float4*)(aG  + k0 + 16);
            av1 = *(const float4*)(aG2 + k0 + 16);
            bv0 = *(const float4*)(bG  + k0 + 16);
            bv1 = *(const float4*)(bG2 + k0 + 16);
        }

#pragma unroll
        for (int k = 0; k < 16; k++) {
            float4 a0 = *(const float4*)&As[k][ty * 8];
            float4 a1 = *(const float4*)&As[k][ty * 8 + 4];
            float4 b0 = *(const float4*)&Bs[k][tx * 8];
            float4 b1 = *(const float4*)&Bs[k][tx * 8 + 4];
            ull bb[4] = { pack2(b0.x, b0.y), pack2(b0.z, b0.w),
                          pack2(b1.x, b1.y), pack2(b1.z, b1.w) };
            float ar[8] = { a0.x, a0.y, a0.z, a0.w, a1.x, a1.y, a1.z, a1.w };
#pragma unroll
            for (int i = 0; i < 8; i++) {
                ull aa = pack2(ar[i], ar[i]);
#pragma unroll
                for (int jp = 0; jp < 4; jp++)
                    acc[i][jp] = fma2(aa, bb[jp], acc[i][jp]);
            }
        }
        __syncthreads();
    }

    // -------- epilogue: bias -> relu -> residual add -> store --------
    float bv[8];
    const bool hasb = (bias != nullptr);
    if (hasb) {
        float4 t0 = *(const float4*)(bias + n0 + tx * 8);
        float4 t1 = *(const float4*)(bias + n0 + tx * 8 + 4);
        bv[0] = t0.x; bv[1] = t0.y; bv[2] = t0.z; bv[3] = t0.w;
        bv[4] = t1.x; bv[5] = t1.y; bv[6] = t1.z; bv[7] = t1.w;
    }
#pragma unroll
    for (int i = 0; i < 8; i++) {
        size_t off = (size_t)(m0 + ty * 8 + i) * N + n0 + tx * 8;
        float o[8];
#pragma unroll
        for (int jp = 0; jp < 4; jp++) {
            float2 u = unpack2(acc[i][jp]);
            o[2 * jp] = u.x; o[2 * jp + 1] = u.y;
        }
        if (hasb) {
#pragma unroll
            for (int j = 0; j < 8; j++) o[j] += bv[j];
        }
        if (RELU) {
#pragma unroll
            for (int j = 0; j < 8; j++) o[j] = fmaxf(o[j], 0.0f);
        }
        if (add != nullptr) {
            float4 r0 = *(const float4*)(add + off);
            float4 r1 = *(const float4*)(add + off + 4);
            o[0] += r0.x; o[1] += r0.y; o[2] += r0.z; o[3] += r0.w;
            o[4] += r1.x; o[5] += r1.y; o[6] += r1.z; o[7] += r1.w;
        }
        float4 w0 = { o[0], o[1], o[2], o[3] };
        float4 w1 = { o[4], o[5], o[6], o[7] };
        *(float4*)(C + off)     = w0;
        *(float4*)(C + off + 4) = w1;
    }
}

// =============================================================================
// Flash attention: per (b, h, 32-row q block). 128 threads.
// Thread (r = tid>>2, cg = tid&3): owns q row r; S cols {4*cc+cg}; O cols
// d in {4*(cg+4*j)..+3}. Online softmax with packed f32x2 math.
// =============================================================================
__global__ __launch_bounds__(128)
void attn_k(const float* __restrict__ qkv, float* __restrict__ out)
{
    __shared__ float ks[64][68];
    __shared__ float vs[64][68];
    __shared__ float ps[32][68];

    const int b  = blockIdx.z;
    const int h  = blockIdx.y;
    const int qb = blockIdx.x;
    const int tid = threadIdx.x;
    const int r  = tid >> 2;
    const int cg = tid & 3;

    // q row in registers, packed as 32 f32x2 pairs
    const float* qrow = qkv + ((size_t)(b * SEQ + qb * 32 + r)) * (3 * CM) + h * HDIM;
    ull q2[32];
#pragma unroll
    for (int i = 0; i < 16; i++) {
        float4 t4 = *(const float4*)(qrow + i * 4);
        q2[2 * i]     = pack2(t4.x, t4.y);
        q2[2 * i + 1] = pack2(t4.z, t4.w);
    }

    ull acc[4][2];
#pragma unroll
    for (int j = 0; j < 4; j++) { acc[j][0] = 0ull; acc[j][1] = 0ull; }
    float mrow = -1e30f, lrow = 0.0f;

    const float* kbase = qkv + (size_t)b * SEQ * (3 * CM) + CM + h * HDIM;

    for (int jt = 0; jt < SEQ / 64; jt++) {
        // stage K/V tiles (64x64 each)
#pragma unroll
        for (int i = 0; i < 8; i++) {
            int idx = tid + i * 128;
            int rr = idx >> 4;
            int c4 = (idx & 15) << 2;
            const float* kp = kbase + (size_t)(jt * 64 + rr) * (3 * CM) + c4;
            *(float4*)&ks[rr][c4] = *(const float4*)kp;
            *(float4*)&vs[rr][c4] = *(const float4*)(kp + CM);
        }
        __syncthreads();

        // ---- S = q . k^T * scale ----
        float s[16];
#pragma unroll
        for (int cc = 0; cc < 16; cc++) {
            int c = 4 * cc + cg;
            const ull* kr = (const ull*)&ks[c][0];
            ull a = 0ull;
#pragma unroll
            for (int dd = 0; dd < 32; dd++) a = fma2(q2[dd], kr[dd], a);
            float2 af = unpack2(a);
            s[cc] = (af.x + af.y) * 0.125f;   // D^{-0.5} = 1/8
        }

        // ---- online softmax update ----
        float mloc = s[0];
#pragma unroll
        for (int cc = 1; cc < 16; cc++) mloc = fmaxf(mloc, s[cc]);
        mloc = fmaxf(mloc, __shfl_xor_sync(0xffffffffu, mloc, 1));
        mloc = fmaxf(mloc, __shfl_xor_sync(0xffffffffu, mloc, 2));
        float mnew = fmaxf(mrow, mloc);
        float corr = __expf(mrow - mnew);
        float ls = 0.0f;
#pragma unroll
        for (int cc = 0; cc < 16; cc++) {
            float p = __expf(s[cc] - mnew);
            ls += p;
            ps[r][4 * cc + cg] = p;
        }
        ls += __shfl_xor_sync(0xffffffffu, ls, 1);
        ls += __shfl_xor_sync(0xffffffffu, ls, 2);
        lrow = lrow * corr + ls;
        mrow = mnew;
        ull c2 = pack2(corr, corr);
#pragma unroll
        for (int j = 0; j < 4; j++) {
            acc[j][0] = mul2(acc[j][0], c2);
            acc[j][1] = mul2(acc[j][1], c2);
        }
        __syncwarp();   // ps produced/consumed within the same warp

        // ---- O += P . V ----
#pragma unroll 8
        for (int c = 0; c < 64; c++) {
            float pv = ps[r][c];
            ull pvv = pack2(pv, pv);
#pragma unroll
            for (int j = 0; j < 4; j++) {
                const ull* vp = (const ull*)&vs[c][4 * (cg + 4 * j)];
                acc[j][0] = fma2(pvv, vp[0], acc[j][0]);
                acc[j][1] = fma2(pvv, vp[1], acc[j][1]);
            }
        }
        __syncthreads();
    }

    // ---- finalize: O / l, write [b, n, h*64+d] ----
    float invl = 1.0f / lrow;
    float* orow = out + ((size_t)(b * SEQ + qb * 32 + r)) * CM + h * HDIM;
#pragma unroll
    for (int j = 0; j < 4; j++) {
        float2 x0 = unpack2(acc[j][0]);
        float2 x1 = unpack2(acc[j][1]);
        float4 o = { x0.x * invl, x0.y * invl, x1.x * invl, x1.y * invl };
        *(float4*)(orow + 4 * (cg + 4 * j)) = o;
    }
}

// =============================================================================
// LayerNorm over last dim (1024). One block per row, 256 threads x float4.
// =============================================================================
__global__ __launch_bounds__(256)
void ln_k(const float* __restrict__ in, const float* __restrict__ gamma,
          const float* __restrict__ beta, float* __restrict__ out)
{
    const int row = blockIdx.x;
    const int tid = threadIdx.x;
    const float4 v = ((const float4*)(in + (size_t)row * CM))[tid];

    float s  = v.x + v.y + v.z + v.w;
    float ss = v.x * v.x + v.y * v.y + v.z * v.z + v.w * v.w;
#pragma unroll
    for (int o = 16; o > 0; o >>= 1) {
        s  += __shfl_xor_sync(0xffffffffu, s,  o);
        ss += __shfl_xor_sync(0xffffffffu, ss, o);
    }
    __shared__ float rs[8], rq[8];
    if ((tid & 31) == 0) { rs[tid >> 5] = s; rq[tid >> 5] = ss; }
    __syncthreads();
    float tot = 0.0f, totq = 0.0f;
#pragma unroll
    for (int i = 0; i < 8; i++) { tot += rs[i]; totq += rq[i]; }

    const float mean = tot * (1.0f / CM);
    const float var  = totq * (1.0f / CM) - mean * mean;
    const float inv  = rsqrtf(var + 1e-5f);

    const float4 g4 = ((const float4*)gamma)[tid];
    const float4 b4 = ((const float4*)beta)[tid];
    float4 o;
    o.x = (v.x - mean) * inv * g4.x + b4.x;
    o.y = (v.y - mean) * inv * g4.y + b4.y;
    o.z = (v.z - mean) * inv * g4.z + b4.z;
    o.w = (v.w - mean) * inv * g4.w + b4.w;
    ((float4*)(out + (size_t)row * CM))[tid] = o;
}

// =============================================================================
// launch
// =============================================================================
extern "C" void kernel_launch(void* const* d_in, const int* in_sizes, int n_in,
                              void* d_out, int out_size)
{
    (void)in_sizes; (void)n_in; (void)out_size;
    const float* src   = (const float*)d_in[0];
    const float* wqkv  = (const float*)d_in[1];
    const float* wproj = (const float*)d_in[2];
    const float* bproj = (const float*)d_in[3];
    const float* w1    = (const float*)d_in[4];
    const float* b1    = (const float*)d_in[5];
    const float* w2    = (const float*)d_in[6];
    const float* b2    = (const float*)d_in[7];
    const float* g1    = (const float*)d_in[8];
    const float* be1   = (const float*)d_in[9];
    const float* g2    = (const float*)d_in[10];
    const float* be2   = (const float*)d_in[11];
    float* out = (float*)d_out;

    float *qkv, *attn, *res, *x, *ff;
    cudaGetSymbolAddress((void**)&qkv,  g_qkv);
    cudaGetSymbolAddress((void**)&attn, g_attn);
    cudaGetSymbolAddress((void**)&res,  g_res);
    cudaGetSymbolAddress((void**)&x,    g_x);
    cudaGetSymbolAddress((void**)&ff,   g_ff);

    // 1) QKV projection: [4096,1024] x [3072,1024]^T -> [4096,3072]
    gemm_nt<0><<<dim3(3 * CM / 128, MTOT / 128), 256>>>(
        src, wqkv, nullptr, nullptr, qkv, MTOT, 3 * CM, CM);

    // 2) attention -> [B,N,C] head-concat layout
    attn_k<<<dim3(SEQ / 32, NHEAD, NB), 128>>>(qkv, attn);

    // 3) output projection + bias + residual(src)
    gemm_nt<0><<<dim3(CM / 128, MTOT / 128), 256>>>(
        attn, wproj, bproj, src, res, MTOT, CM, CM);

    // 4) LayerNorm 1
    ln_k<<<MTOT, 256>>>(res, g1, be1, x);

    // 5) FFN up: relu(x @ w1^T + b1) -> [4096,4096]
    gemm_nt<1><<<dim3(FF / 128, MTOT / 128), 256>>>(
        x, w1, b1, nullptr, ff, MTOT, FF, CM);

    // 6) FFN down + bias + residual(x)
    gemm_nt<0><<<dim3(CM / 128, MTOT / 128), 256>>>(
        ff, w2, b2, x, res, MTOT, CM, FF);

    // 7) LayerNorm 2 -> output
    ln_k<<<MTOT, 256>>>(res, g2, be2, out);
}

// round 7
// speedup vs baseline: 1.4576x; 1.4576x over previous
#include <cuda_runtime.h>
#include <cuda_bf16.h>
#include <cstdint>

typedef unsigned long long ull;

#define SEQ   2048
#define NB    2
#define CM    1024
#define NHEAD 16
#define HDIM  64
#define FF    4096
#define MTOT  (NB*SEQ)   // 4096 rows total

// ---------------- scratch (static device globals; no allocation) -------------
__device__ float g_qkv[(size_t)MTOT * 3 * CM];   // 50 MB
__device__ float g_attn[(size_t)MTOT * CM];      // 16 MB
__device__ float g_res[(size_t)MTOT * CM];       // 16 MB
__device__ float g_x[(size_t)MTOT * CM];         // 16 MB
__device__ float g_ff[(size_t)MTOT * FF];        // 64 MB
// bf16 hi/lo staging for tensor-core GEMMs
__device__ __nv_bfloat16 g_ah[(size_t)MTOT * FF];  // 32 MB
__device__ __nv_bfloat16 g_al[(size_t)MTOT * FF];  // 32 MB
__device__ __nv_bfloat16 g_bh[(size_t)FF * CM];    //  8 MB
__device__ __nv_bfloat16 g_bl[(size_t)FF * CM];    //  8 MB

// ---------------- packed f32x2 helpers (attention kernel) -------------------
__device__ __forceinline__ ull pack2(float x, float y) {
    ull r; asm("mov.b64 %0, {%1, %2};" : "=l"(r) : "f"(x), "f"(y)); return r;
}
__device__ __forceinline__ float2 unpack2(ull v) {
    float2 r; asm("mov.b64 {%0, %1}, %2;" : "=f"(r.x), "=f"(r.y) : "l"(v)); return r;
}
__device__ __forceinline__ ull fma2(ull a, ull b, ull c) {
    ull d; asm("fma.rn.f32x2 %0, %1, %2, %3;" : "=l"(d) : "l"(a), "l"(b), "l"(c)); return d;
}
__device__ __forceinline__ ull mul2(ull a, ull b) {
    ull d; asm("mul.rn.f32x2 %0, %1, %2;" : "=l"(d) : "l"(a), "l"(b)); return d;
}

// ---------------- mma.sync / ldmatrix / cp.async primitives -----------------
__device__ __forceinline__ uint32_t smem_u32(const void* p) {
    uint32_t a;
    asm("{ .reg .u64 t; cvta.to.shared.u64 t, %1; cvt.u32.u64 %0, t; }" : "=r"(a) : "l"(p));
    return a;
}
__device__ __forceinline__ void cpa16(uint32_t dst, const void* src) {
    asm volatile("cp.async.cg.shared.global [%0], [%1], 16;" :: "r"(dst), "l"(src));
}
#define CPA_COMMIT() asm volatile("cp.async.commit_group;" ::: "memory")

#define LDMX4(d, a) \
    asm volatile("ldmatrix.sync.aligned.m8n8.x4.shared.b16 {%0,%1,%2,%3}, [%4];" \
        : "=r"((d)[0]), "=r"((d)[1]), "=r"((d)[2]), "=r"((d)[3]) : "r"(a))

__device__ __forceinline__ void mma16816(float* d, const uint32_t* a,
                                         uint32_t b0, uint32_t b1) {
    asm volatile(
        "mma.sync.aligned.m16n8k16.row.col.f32.bf16.bf16.f32 "
        "{%0,%1,%2,%3}, {%4,%5,%6,%7}, {%8,%9}, {%0,%1,%2,%3};"
        : "+f"(d[0]), "+f"(d[1]), "+f"(d[2]), "+f"(d[3])
        : "r"(a[0]), "r"(a[1]), "r"(a[2]), "r"(a[3]), "r"(b0), "r"(b1));
}

// =============================================================================
// fp32 -> (bf16 hi, bf16 lo) split conversion
// =============================================================================
__global__ __launch_bounds__(256)
void cvt_hilo(const float* __restrict__ x, __nv_bfloat16* __restrict__ hi,
              __nv_bfloat16* __restrict__ lo, int n4)
{
    int i = blockIdx.x * blockDim.x + threadIdx.x;
    if (i >= n4) return;
    float4 v = ((const float4*)x)[i];
    __nv_bfloat16 ha = __float2bfloat16(v.x);
    __nv_bfloat16 hb = __float2bfloat16(v.y);
    __nv_bfloat16 hc = __float2bfloat16(v.z);
    __nv_bfloat16 hd = __float2bfloat16(v.w);
    __nv_bfloat16 la = __float2bfloat16(v.x - __bfloat162float(ha));
    __nv_bfloat16 lb = __float2bfloat16(v.y - __bfloat162float(hb));
    __nv_bfloat16 lc = __float2bfloat16(v.z - __bfloat162float(hc));
    __nv_bfloat16 ld = __float2bfloat16(v.w - __bfloat162float(hd));
    __nv_bfloat162* hp = (__nv_bfloat162*)(hi + 4 * (size_t)i);
    __nv_bfloat162* lp = (__nv_bfloat162*)(lo + 4 * (size_t)i);
    hp[0] = __nv_bfloat162(ha, hb); hp[1] = __nv_bfloat162(hc, hd);
    lp[0] = __nv_bfloat162(la, lb); lp[1] = __nv_bfloat162(lc, ld);
}

// =============================================================================
// mma.sync GEMM: C[M,N] = A[M,K] * B[N,K]^T   (split-bf16: AhBh + AhBl + AlBh)
// Block: 128x128x32, 256 threads = 8 warps (2 x 4), warp tile 64x32.
// SMEM: per stage 4 tiles [128][40] bf16 (Ah,Al,Bh,Bl), double buffered.
// =============================================================================
#define GS   40                      // padded bf16 stride (80 B rows)
#define GTILE (128 * GS * 2)         // 10240 B
#define GSTG  (4 * GTILE)            // 40960 B per stage
#define GEMM_SMEM (2 * GSTG)         // 81920 B

template <int RELU>
__global__ __launch_bounds__(256, 1)
void gemm_mma(const __nv_bfloat16* __restrict__ Ah, const __nv_bfloat16* __restrict__ Al,
              const __nv_bfloat16* __restrict__ Bh, const __nv_bfloat16* __restrict__ Bl,
              const float* __restrict__ bias, const float* __restrict__ add,
              float* __restrict__ C, int M, int N, int K)
{
    extern __shared__ char smem[];
    const uint32_t sb = smem_u32(smem);
    const int tid  = threadIdx.x;
    const int lane = tid & 31;
    const int wid  = tid >> 5;
    const int wm   = wid & 1;       // 2 warps along M
    const int wn   = wid >> 1;      // 4 warps along N
    const int m0   = blockIdx.y * 128;
    const int n0   = blockIdx.x * 128;
    const int nch  = K >> 5;

    // ldmatrix lane-address components
    const int grp = lane >> 3;
    const int rA  = (lane & 7) + ((grp & 1) << 3);   // A: m0-7/m8-15 x k0/k8
    const int cA  = (grp >> 1) << 3;
    const int rB  = (lane & 7) + ((grp >> 1) << 3);  // B: n0-7/n8-15 x k0/k8
    const int cB  = (grp & 1) << 3;

    float acc[4][4][4];
#pragma unroll
    for (int i = 0; i < 4; i++)
#pragma unroll
        for (int j = 0; j < 4; j++)
#pragma unroll
            for (int q = 0; q < 4; q++) acc[i][j][q] = 0.0f;

    // ---- loader: 512 16B units per tile; thread does 2 units x 4 tiles ----
    auto load_chunk = [&](int kc, int st) {
        const uint32_t base = sb + st * GSTG;
        const int k0 = kc << 5;
#pragma unroll
        for (int h = 0; h < 2; h++) {
            int u   = tid + h * 256;
            int row = u >> 2, seg = u & 3;
            uint32_t doff = (uint32_t)(row * (GS * 2) + seg * 16);
            size_t ga = (size_t)(m0 + row) * K + k0 + seg * 8;
            size_t gb = (size_t)(n0 + row) * K + k0 + seg * 8;
            cpa16(base + 0 * GTILE + doff, Ah + ga);
            cpa16(base + 1 * GTILE + doff, Al + ga);
            cpa16(base + 2 * GTILE + doff, Bh + gb);
            cpa16(base + 3 * GTILE + doff, Bl + gb);
        }
    };

    load_chunk(0, 0); CPA_COMMIT();
    load_chunk(1, 1); CPA_COMMIT();

    const uint32_t laneA = (uint32_t)((rA * GS + cA) * 2);
    const uint32_t laneB = (uint32_t)((rB * GS + cB) * 2);

    for (int c = 0; c < nch; ++c) {
        const int s = c & 1;
        if (c + 1 < nch) asm volatile("cp.async.wait_group 1;" ::: "memory");
        else             asm volatile("cp.async.wait_group 0;" ::: "memory");
        __syncthreads();

        const uint32_t stb = sb + s * GSTG;
        const uint32_t aH = stb + 0 * GTILE + (uint32_t)(wm * 64 * GS * 2) + laneA;
        const uint32_t aL = stb + 1 * GTILE + (uint32_t)(wm * 64 * GS * 2) + laneA;
        const uint32_t bH = stb + 2 * GTILE + (uint32_t)(wn * 32 * GS * 2) + laneB;
        const uint32_t bL = stb + 3 * GTILE + (uint32_t)(wn * 32 * GS * 2) + laneB;

#pragma unroll
        for (int ks = 0; ks < 2; ks++) {
            const uint32_t ko = (uint32_t)(ks * 16 * 2);
            uint32_t fah[4][4], fal[4][4], fbh[2][4], fbl[2][4];
#pragma unroll
            for (int mt = 0; mt < 4; mt++) {
                LDMX4(fah[mt], aH + (uint32_t)(mt * 16 * GS * 2) + ko);
                LDMX4(fal[mt], aL + (uint32_t)(mt * 16 * GS * 2) + ko);
            }
#pragma unroll
            for (int p = 0; p < 2; p++) {
                LDMX4(fbh[p], bH + (uint32_t)(p * 16 * GS * 2) + ko);
                LDMX4(fbl[p], bL + (uint32_t)(p * 16 * GS * 2) + ko);
            }
#pragma unroll
            for (int mt = 0; mt < 4; mt++) {
#pragma unroll
                for (int nt = 0; nt < 4; nt++) {
                    const int p = nt >> 1, q = nt & 1;
                    mma16816(acc[mt][nt], fah[mt], fbh[p][2 * q], fbh[p][2 * q + 1]);
                    mma16816(acc[mt][nt], fah[mt], fbl[p][2 * q], fbl[p][2 * q + 1]);
                    mma16816(acc[mt][nt], fal[mt], fbh[p][2 * q], fbh[p][2 * q + 1]);
                }
            }
        }
        __syncthreads();
        if (c + 2 < nch) { load_chunk(c + 2, s); CPA_COMMIT(); }
    }

    // ---- epilogue: bias -> relu -> residual -> store ----
    const int qr = lane >> 2;
    const int qc = (lane & 3) * 2;
    const bool hasb = (bias != nullptr);
    const bool hasa = (add  != nullptr);
#pragma unroll
    for (int nt = 0; nt < 4; nt++) {
        const int n = n0 + wn * 32 + nt * 8 + qc;
        float2 bb = make_float2(0.f, 0.f);
        if (hasb) bb = *(const float2*)(bias + n);
#pragma unroll
        for (int mt = 0; mt < 4; mt++) {
#pragma unroll
            for (int half = 0; half < 2; half++) {
                const int m = m0 + wm * 64 + mt * 16 + qr + half * 8;
                float2 o = make_float2(acc[mt][nt][2 * half]     + bb.x,
                                       acc[mt][nt][2 * half + 1] + bb.y);
                if (RELU) { o.x = fmaxf(o.x, 0.f); o.y = fmaxf(o.y, 0.f); }
                if (hasa) {
                    float2 r = *(const float2*)(add + (size_t)m * N + n);
                    o.x += r.x; o.y += r.y;
                }
                *(float2*)(C + (size_t)m * N + n) = o;
            }
        }
    }
}

// =============================================================================
// Flash attention (scalar f32x2, fma-bound) — unchanged from R5
// =============================================================================
__global__ __launch_bounds__(128)
void attn_k(const float* __restrict__ qkv, float* __restrict__ out)
{
    __shared__ float ks[64][68];
    __shared__ float vs[64][68];
    __shared__ float ps[32][68];

    const int b  = blockIdx.z;
    const int h  = blockIdx.y;
    const int qb = blockIdx.x;
    const int tid = threadIdx.x;
    const int r  = tid >> 2;
    const int cg = tid & 3;

    const float* qrow = qkv + ((size_t)(b * SEQ + qb * 32 + r)) * (3 * CM) + h * HDIM;
    ull q2[32];
#pragma unroll
    for (int i = 0; i < 16; i++) {
        float4 t4 = *(const float4*)(qrow + i * 4);
        q2[2 * i]     = pack2(t4.x, t4.y);
        q2[2 * i + 1] = pack2(t4.z, t4.w);
    }

    ull acc[4][2];
#pragma unroll
    for (int j = 0; j < 4; j++) { acc[j][0] = 0ull; acc[j][1] = 0ull; }
    float mrow = -1e30f, lrow = 0.0f;

    const float* kbase = qkv + (size_t)b * SEQ * (3 * CM) + CM + h * HDIM;

    for (int jt = 0; jt < SEQ / 64; jt++) {
#pragma unroll
        for (int i = 0; i < 8; i++) {
            int idx = tid + i * 128;
            int rr = idx >> 4;
            int c4 = (idx & 15) << 2;
            const float* kp = kbase + (size_t)(jt * 64 + rr) * (3 * CM) + c4;
            *(float4*)&ks[rr][c4] = *(const float4*)kp;
            *(float4*)&vs[rr][c4] = *(const float4*)(kp + CM);
        }
        __syncthreads();

        float s[16];
#pragma unroll
        for (int cc = 0; cc < 16; cc++) {
            int c = 4 * cc + cg;
            const ull* kr = (const ull*)&ks[c][0];
            ull a = 0ull;
#pragma unroll
            for (int dd = 0; dd < 32; dd++) a = fma2(q2[dd], kr[dd], a);
            float2 af = unpack2(a);
            s[cc] = (af.x + af.y) * 0.125f;
        }

        float mloc = s[0];
#pragma unroll
        for (int cc = 1; cc < 16; cc++) mloc = fmaxf(mloc, s[cc]);
        mloc = fmaxf(mloc, __shfl_xor_sync(0xffffffffu, mloc, 1));
        mloc = fmaxf(mloc, __shfl_xor_sync(0xffffffffu, mloc, 2));
        float mnew = fmaxf(mrow, mloc);
        float corr = __expf(mrow - mnew);
        float ls = 0.0f;
#pragma unroll
        for (int cc = 0; cc < 16; cc++) {
            float p = __expf(s[cc] - mnew);
            ls += p;
            ps[r][4 * cc + cg] = p;
        }
        ls += __shfl_xor_sync(0xffffffffu, ls, 1);
        ls += __shfl_xor_sync(0xffffffffu, ls, 2);
        lrow = lrow * corr + ls;
        mrow = mnew;
        ull c2 = pack2(corr, corr);
#pragma unroll
        for (int j = 0; j < 4; j++) {
            acc[j][0] = mul2(acc[j][0], c2);
            acc[j][1] = mul2(acc[j][1], c2);
        }
        __syncwarp();

#pragma unroll 8
        for (int c = 0; c < 64; c++) {
            float pv = ps[r][c];
            ull pvv = pack2(pv, pv);
#pragma unroll
            for (int j = 0; j < 4; j++) {
                const ull* vp = (const ull*)&vs[c][4 * (cg + 4 * j)];
                acc[j][0] = fma2(pvv, vp[0], acc[j][0]);
                acc[j][1] = fma2(pvv, vp[1], acc[j][1]);
            }
        }
        __syncthreads();
    }

    float invl = 1.0f / lrow;
    float* orow = out + ((size_t)(b * SEQ + qb * 32 + r)) * CM + h * HDIM;
#pragma unroll
    for (int j = 0; j < 4; j++) {
        float2 x0 = unpack2(acc[j][0]);
        float2 x1 = unpack2(acc[j][1]);
        float4 o = { x0.x * invl, x0.y * invl, x1.x * invl, x1.y * invl };
        *(float4*)(orow + 4 * (cg + 4 * j)) = o;
    }
}

// =============================================================================
// LayerNorm over last dim (1024). One block per row, 256 threads x float4.
// =============================================================================
__global__ __launch_bounds__(256)
void ln_k(const float* __restrict__ in, const float* __restrict__ gamma,
          const float* __restrict__ beta, float* __restrict__ out)
{
    const int row = blockIdx.x;
    const int tid = threadIdx.x;
    const float4 v = ((const float4*)(in + (size_t)row * CM))[tid];

    float s  = v.x + v.y + v.z + v.w;
    float ss = v.x * v.x + v.y * v.y + v.z * v.z + v.w * v.w;
#pragma unroll
    for (int o = 16; o > 0; o >>= 1) {
        s  += __shfl_xor_sync(0xffffffffu, s,  o);
        ss += __shfl_xor_sync(0xffffffffu, ss, o);
    }
    __shared__ float rs[8], rq[8];
    if ((tid & 31) == 0) { rs[tid >> 5] = s; rq[tid >> 5] = ss; }
    __syncthreads();
    float tot = 0.0f, totq = 0.0f;
#pragma unroll
    for (int i = 0; i < 8; i++) { tot += rs[i]; totq += rq[i]; }

    const float mean = tot * (1.0f / CM);
    const float var  = totq * (1.0f / CM) - mean * mean;
    const float inv  = rsqrtf(var + 1e-5f);

    const float4 g4 = ((const float4*)gamma)[tid];
    const float4 b4 = ((const float4*)beta)[tid];
    float4 o;
    o.x = (v.x - mean) * inv * g4.x + b4.x;
    o.y = (v.y - mean) * inv * g4.y + b4.y;
    o.z = (v.z - mean) * inv * g4.z + b4.z;
    o.w = (v.w - mean) * inv * g4.w + b4.w;
    ((float4*)(out + (size_t)row * CM))[tid] = o;
}

// =============================================================================
// launch
// =============================================================================
static inline void cvt(const float* x, __nv_bfloat16* hi, __nv_bfloat16* lo, size_t n) {
    int n4 = (int)(n / 4);
    cvt_hilo<<<(n4 + 255) / 256, 256>>>(x, hi, lo, n4);
}

extern "C" void kernel_launch(void* const* d_in, const int* in_sizes, int n_in,
                              void* d_out, int out_size)
{
    (void)in_sizes; (void)n_in; (void)out_size;
    const float* src   = (const float*)d_in[0];
    const float* wqkv  = (const float*)d_in[1];
    const float* wproj = (const float*)d_in[2];
    const float* bproj = (const float*)d_in[3];
    const float* w1    = (const float*)d_in[4];
    const float* b1    = (const float*)d_in[5];
    const float* w2    = (const float*)d_in[6];
    const float* b2    = (const float*)d_in[7];
    const float* g1    = (const float*)d_in[8];
    const float* be1   = (const float*)d_in[9];
    const float* g2    = (const float*)d_in[10];
    const float* be2   = (const float*)d_in[11];
    float* out = (float*)d_out;

    float *qkv, *attn, *res, *x, *ff;
    __nv_bfloat16 *ah, *al, *bh, *bl;
    cudaGetSymbolAddress((void**)&qkv,  g_qkv);
    cudaGetSymbolAddress((void**)&attn, g_attn);
    cudaGetSymbolAddress((void**)&res,  g_res);
    cudaGetSymbolAddress((void**)&x,    g_x);
    cudaGetSymbolAddress((void**)&ff,   g_ff);
    cudaGetSymbolAddress((void**)&ah,   g_ah);
    cudaGetSymbolAddress((void**)&al,   g_al);
    cudaGetSymbolAddress((void**)&bh,   g_bh);
    cudaGetSymbolAddress((void**)&bl,   g_bl);

    cudaFuncSetAttribute(gemm_mma<0>, cudaFuncAttributeMaxDynamicSharedMemorySize, GEMM_SMEM);
    cudaFuncSetAttribute(gemm_mma<1>, cudaFuncAttributeMaxDynamicSharedMemorySize, GEMM_SMEM);

    // 1) QKV projection: [4096,1024] x [3072,1024]^T -> [4096,3072]
    cvt(src,  ah, al, (size_t)MTOT * CM);
    cvt(wqkv, bh, bl, (size_t)3 * CM * CM);
    gemm_mma<0><<<dim3(3 * CM / 128, MTOT / 128), 256, GEMM_SMEM>>>(
        ah, al, bh, bl, nullptr, nullptr, qkv, MTOT, 3 * CM, CM);

    // 2) attention -> [B,N,C] head-concat layout
    attn_k<<<dim3(SEQ / 32, NHEAD, NB), 128>>>(qkv, attn);

    // 3) output projection + bias + residual(src)
    cvt(attn,  ah, al, (size_t)MTOT * CM);
    cvt(wproj, bh, bl, (size_t)CM * CM);
    gemm_mma<0><<<dim3(CM / 128, MTOT / 128), 256, GEMM_SMEM>>>(
        ah, al, bh, bl, bproj, src, res, MTOT, CM, CM);

    // 4) LayerNorm 1
    ln_k<<<MTOT, 256>>>(res, g1, be1, x);

    // 5) FFN up: relu(x @ w1^T + b1) -> [4096,4096]
    cvt(x,  ah, al, (size_t)MTOT * CM);
    cvt(w1, bh, bl, (size_t)FF * CM);
    gemm_mma<1><<<dim3(FF / 128, MTOT / 128), 256, GEMM_SMEM>>>(
        ah, al, bh, bl, b1, nullptr, ff, MTOT, FF, CM);

    // 6) FFN down + bias + residual(x)
    cvt(ff, ah, al, (size_t)MTOT * FF);
    cvt(w2, bh, bl, (size_t)CM * FF);
    gemm_mma<0><<<dim3(CM / 128, MTOT / 128), 256, GEMM_SMEM>>>(
        ah, al, bh, bl, b2, x, res, MTOT, CM, FF);

    // 7) LayerNorm 2 -> output
    ln_k<<<MTOT, 256>>>(res, g2, be2, out);
}

// round 9
// speedup vs baseline: 2.9420x; 2.0185x over previous
#include <cuda_runtime.h>
#include <cuda_bf16.h>
#include <cstdint>

typedef unsigned long long ull;

#define SEQ   2048
#define NB    2
#define CM    1024
#define NHEAD 16
#define HDIM  64
#define FF    4096
#define MTOT  (NB*SEQ)   // 4096 rows total

// ---------------- scratch (static device globals; no allocation) -------------
__device__ float g_qkv[(size_t)MTOT * 3 * CM];   // 50 MB
__device__ float g_attn[(size_t)MTOT * CM];      // 16 MB
__device__ float g_res[(size_t)MTOT * CM];       // 16 MB
__device__ float g_x[(size_t)MTOT * CM];         // 16 MB
__device__ float g_ff[(size_t)MTOT * FF];        // 64 MB
// bf16 hi/lo staging for tensor-core GEMMs / attention
__device__ __nv_bfloat16 g_ah[(size_t)MTOT * FF];  // 32 MB
__device__ __nv_bfloat16 g_al[(size_t)MTOT * FF];  // 32 MB
__device__ __nv_bfloat16 g_bh[(size_t)FF * CM];    //  8 MB
__device__ __nv_bfloat16 g_bl[(size_t)FF * CM];    //  8 MB

// ---------------- mma.sync / ldmatrix / cp.async primitives -----------------
__device__ __forceinline__ uint32_t smem_u32(const void* p) {
    uint32_t a;
    asm("{ .reg .u64 t; cvta.to.shared.u64 t, %1; cvt.u32.u64 %0, t; }" : "=r"(a) : "l"(p));
    return a;
}
__device__ __forceinline__ void cpa16(uint32_t dst, const void* src) {
    asm volatile("cp.async.cg.shared.global [%0], [%1], 16;" :: "r"(dst), "l"(src));
}
#define CPA_COMMIT() asm volatile("cp.async.commit_group;" ::: "memory")

#define LDMX4(d, a) \
    asm volatile("ldmatrix.sync.aligned.m8n8.x4.shared.b16 {%0,%1,%2,%3}, [%4];" \
        : "=r"((d)[0]), "=r"((d)[1]), "=r"((d)[2]), "=r"((d)[3]) : "r"(a))
#define LDMT4(d, a) \
    asm volatile("ldmatrix.sync.aligned.m8n8.x4.trans.shared.b16 {%0,%1,%2,%3}, [%4];" \
        : "=r"((d)[0]), "=r"((d)[1]), "=r"((d)[2]), "=r"((d)[3]) : "r"(a))

__device__ __forceinline__ void mma16816(float* d, const uint32_t* a,
                                         uint32_t b0, uint32_t b1) {
    asm volatile(
        "mma.sync.aligned.m16n8k16.row.col.f32.bf16.bf16.f32 "
        "{%0,%1,%2,%3}, {%4,%5,%6,%7}, {%8,%9}, {%0,%1,%2,%3};"
        : "+f"(d[0]), "+f"(d[1]), "+f"(d[2]), "+f"(d[3])
        : "r"(a[0]), "r"(a[1]), "r"(a[2]), "r"(a[3]), "r"(b0), "r"(b1));
}

// pack two fp32 into bf16x2 (lo = first element)
#define PKBF2(u, lo, hi) \
    asm("cvt.rn.bf16x2.f32 %0, %1, %2;" : "=r"(u) : "f"(hi), "f"(lo))

// =============================================================================
// fp32 -> (bf16 hi, bf16 lo) split conversion
// =============================================================================
__global__ __launch_bounds__(256)
void cvt_hilo(const float* __restrict__ x, __nv_bfloat16* __restrict__ hi,
              __nv_bfloat16* __restrict__ lo, int n4)
{
    int i = blockIdx.x * blockDim.x + threadIdx.x;
    if (i >= n4) return;
    float4 v = ((const float4*)x)[i];
    __nv_bfloat16 ha = __float2bfloat16(v.x);
    __nv_bfloat16 hb = __float2bfloat16(v.y);
    __nv_bfloat16 hc = __float2bfloat16(v.z);
    __nv_bfloat16 hd = __float2bfloat16(v.w);
    __nv_bfloat16 la = __float2bfloat16(v.x - __bfloat162float(ha));
    __nv_bfloat16 lb = __float2bfloat16(v.y - __bfloat162float(hb));
    __nv_bfloat16 lc = __float2bfloat16(v.z - __bfloat162float(hc));
    __nv_bfloat16 ld = __float2bfloat16(v.w - __bfloat162float(hd));
    __nv_bfloat162* hp = (__nv_bfloat162*)(hi + 4 * (size_t)i);
    __nv_bfloat162* lp = (__nv_bfloat162*)(lo + 4 * (size_t)i);
    hp[0] = __nv_bfloat162(ha, hb); hp[1] = __nv_bfloat162(hc, hd);
    lp[0] = __nv_bfloat162(la, lb); lp[1] = __nv_bfloat162(lc, ld);
}

// =============================================================================
// mma.sync GEMM: C[M,N] = A[M,K] * B[N,K]^T   (split-bf16: AhBh + AhBl + AlBh)
// Block: 128x128x32, 256 threads = 8 warps (2 x 4), warp tile 64x32.
// =============================================================================
#define GS   40
#define GTILE (128 * GS * 2)
#define GSTG  (4 * GTILE)
#define GEMM_SMEM (2 * GSTG)

template <int RELU>
__global__ __launch_bounds__(256, 1)
void gemm_mma(const __nv_bfloat16* __restrict__ Ah, const __nv_bfloat16* __restrict__ Al,
              const __nv_bfloat16* __restrict__ Bh, const __nv_bfloat16* __restrict__ Bl,
              const float* __restrict__ bias, const float* __restrict__ add,
              float* __restrict__ C, int M, int N, int K)
{
    extern __shared__ char smem[];
    const uint32_t sb = smem_u32(smem);
    const int tid  = threadIdx.x;
    const int lane = tid & 31;
    const int wid  = tid >> 5;
    const int wm   = wid & 1;
    const int wn   = wid >> 1;
    const int m0   = blockIdx.y * 128;
    const int n0   = blockIdx.x * 128;
    const int nch  = K >> 5;

    const int grp = lane >> 3;
    const int rA  = (lane & 7) + ((grp & 1) << 3);
    const int cA  = (grp >> 1) << 3;
    const int rB  = (lane & 7) + ((grp >> 1) << 3);
    const int cB  = (grp & 1) << 3;

    float acc[4][4][4];
#pragma unroll
    for (int i = 0; i < 4; i++)
#pragma unroll
        for (int j = 0; j < 4; j++)
#pragma unroll
            for (int q = 0; q < 4; q++) acc[i][j][q] = 0.0f;

    auto load_chunk = [&](int kc, int st) {
        const uint32_t base = sb + st * GSTG;
        const int k0 = kc << 5;
#pragma unroll
        for (int h = 0; h < 2; h++) {
            int u   = tid + h * 256;
            int row = u >> 2, seg = u & 3;
            uint32_t doff = (uint32_t)(row * (GS * 2) + seg * 16);
            size_t ga = (size_t)(m0 + row) * K + k0 + seg * 8;
            size_t gb = (size_t)(n0 + row) * K + k0 + seg * 8;
            cpa16(base + 0 * GTILE + doff, Ah + ga);
            cpa16(base + 1 * GTILE + doff, Al + ga);
            cpa16(base + 2 * GTILE + doff, Bh + gb);
            cpa16(base + 3 * GTILE + doff, Bl + gb);
        }
    };

    load_chunk(0, 0); CPA_COMMIT();
    load_chunk(1, 1); CPA_COMMIT();

    const uint32_t laneA = (uint32_t)((rA * GS + cA) * 2);
    const uint32_t laneB = (uint32_t)((rB * GS + cB) * 2);

    for (int c = 0; c < nch; ++c) {
        const int s = c & 1;
        if (c + 1 < nch) asm volatile("cp.async.wait_group 1;" ::: "memory");
        else             asm volatile("cp.async.wait_group 0;" ::: "memory");
        __syncthreads();

        const uint32_t stb = sb + s * GSTG;
        const uint32_t aH = stb + 0 * GTILE + (uint32_t)(wm * 64 * GS * 2) + laneA;
        const uint32_t aL = stb + 1 * GTILE + (uint32_t)(wm * 64 * GS * 2) + laneA;
        const uint32_t bH = stb + 2 * GTILE + (uint32_t)(wn * 32 * GS * 2) + laneB;
        const uint32_t bL = stb + 3 * GTILE + (uint32_t)(wn * 32 * GS * 2) + laneB;

#pragma unroll
        for (int ks = 0; ks < 2; ks++) {
            const uint32_t ko = (uint32_t)(ks * 16 * 2);
            uint32_t fah[4][4], fal[4][4], fbh[2][4], fbl[2][4];
#pragma unroll
            for (int mt = 0; mt < 4; mt++) {
                LDMX4(fah[mt], aH + (uint32_t)(mt * 16 * GS * 2) + ko);
                LDMX4(fal[mt], aL + (uint32_t)(mt * 16 * GS * 2) + ko);
            }
#pragma unroll
            for (int p = 0; p < 2; p++) {
                LDMX4(fbh[p], bH + (uint32_t)(p * 16 * GS * 2) + ko);
                LDMX4(fbl[p], bL + (uint32_t)(p * 16 * GS * 2) + ko);
            }
#pragma unroll
            for (int mt = 0; mt < 4; mt++) {
#pragma unroll
                for (int nt = 0; nt < 4; nt++) {
                    const int p = nt >> 1, q = nt & 1;
                    mma16816(acc[mt][nt], fah[mt], fbh[p][2 * q], fbh[p][2 * q + 1]);
                    mma16816(acc[mt][nt], fah[mt], fbl[p][2 * q], fbl[p][2 * q + 1]);
                    mma16816(acc[mt][nt], fal[mt], fbh[p][2 * q], fbh[p][2 * q + 1]);
                }
            }
        }
        __syncthreads();
        if (c + 2 < nch) { load_chunk(c + 2, s); CPA_COMMIT(); }
    }

    const int qr = lane >> 2;
    const int qc = (lane & 3) * 2;
    const bool hasb = (bias != nullptr);
    const bool hasa = (add  != nullptr);
#pragma unroll
    for (int nt = 0; nt < 4; nt++) {
        const int n = n0 + wn * 32 + nt * 8 + qc;
        float2 bb = make_float2(0.f, 0.f);
        if (hasb) bb = *(const float2*)(bias + n);
#pragma unroll
        for (int mt = 0; mt < 4; mt++) {
#pragma unroll
            for (int half = 0; half < 2; half++) {
                const int m = m0 + wm * 64 + mt * 16 + qr + half * 8;
                float2 o = make_float2(acc[mt][nt][2 * half]     + bb.x,
                                       acc[mt][nt][2 * half + 1] + bb.y);
                if (RELU) { o.x = fmaxf(o.x, 0.f); o.y = fmaxf(o.y, 0.f); }
                if (hasa) {
                    float2 r = *(const float2*)(add + (size_t)m * N + n);
                    o.x += r.x; o.y += r.y;
                }
                *(float2*)(C + (size_t)m * N + n) = o;
            }
        }
    }
}

// =============================================================================
// Tensor-core flash attention (mma.sync bf16, split-precision 3-term)
// Block: one (b, h), 128 q rows. 256 threads = 8 warps x 16 q rows.
// K/V tiles 64 keys, hi/lo bf16 in padded smem (stride 72 b16), double-buffered.
// Q fragments register-resident; P stays in registers (S-frag == A-frag map).
// V B-operand via ldmatrix.x4.trans on [key][hdim] tiles.
// =============================================================================
#define AS    72
#define ATILE (64 * AS * 2)        // 9216 B per 64x64 bf16 tile
#define ASTG  (4 * ATILE)          // kh,kl,vh,vl = 36864 B per stage
#define ATTN_SMEM (2 * ASTG)       // 73728 B

__global__ __launch_bounds__(256, 1)
void attn_mma(const __nv_bfloat16* __restrict__ qh,
              const __nv_bfloat16* __restrict__ ql,
              float* __restrict__ out)
{
    extern __shared__ char smem[];
    const uint32_t sb = smem_u32(smem);
    const int tid  = threadIdx.x;
    const int lane = tid & 31;
    const int wid  = tid >> 5;
    const int b  = blockIdx.z;
    const int h  = blockIdx.y;
    const int qt = blockIdx.x;

    const int grp = lane >> 3;
    const int rA  = (lane & 7) + ((grp & 1) << 3);
    const int cA  = (grp >> 1) << 3;
    const int rB  = (lane & 7) + ((grp >> 1) << 3);
    const int cB  = (grp & 1) << 3;

    const size_t tok0 = (size_t)b * SEQ + (size_t)qt * 128;

    // ---- stage Q tile (128 x 64, hi+lo) into smem, build register frags ----
#pragma unroll
    for (int i = 0; i < 4; i++) {
        int u = tid + i * 256;           // 1024 16B units per array
        int r = u >> 3, seg = u & 7;
        const __nv_bfloat16* sh = qh + (tok0 + r) * (3 * CM) + h * HDIM + seg * 8;
        const __nv_bfloat16* sl = ql + (tok0 + r) * (3 * CM) + h * HDIM + seg * 8;
        uint32_t d = (uint32_t)(r * (AS * 2) + seg * 16);
        cpa16(sb + d, sh);
        cpa16(sb + 36864u + d, sl);
    }
    CPA_COMMIT();
    asm volatile("cp.async.wait_group 0;" ::: "memory");
    __syncthreads();

    uint32_t qfh[4][4], qfl[4][4];
#pragma unroll
    for (int c = 0; c < 4; c++) {
        uint32_t a = sb + (uint32_t)(((wid * 16 + rA) * AS + cA + c * 16) * 2);
        LDMX4(qfh[c], a);
        LDMX4(qfl[c], a + 36864u);
    }
    __syncthreads();   // Q frags in regs; smem free for K/V pipeline

    float oacc[8][4];
#pragma unroll
    for (int j = 0; j < 8; j++)
#pragma unroll
        for (int q = 0; q < 4; q++) oacc[j][q] = 0.0f;
    float mrow0 = -1e30f, mrow1 = -1e30f, lrow0 = 0.0f, lrow1 = 0.0f;

    // loader: 4 arrays x 64 rows; thread owns one row of one array, 8 cpa16
    auto load_kv = [&](int kt, int st) {
        const int t = tid >> 6;          // 0=kh 1=kl 2=vh 3=vl
        const int r = tid & 63;
        size_t row = ((size_t)b * SEQ + kt * 64 + r) * (3 * CM) + h * HDIM;
        const __nv_bfloat16* src;
        if      (t == 0) src = qh + row + CM;
        else if (t == 1) src = ql + row + CM;
        else if (t == 2) src = qh + row + 2 * CM;
        else             src = ql + row + 2 * CM;
        uint32_t dst = sb + st * ASTG + t * ATILE + (uint32_t)(r * AS * 2);
#pragma unroll
        for (int s = 0; s < 8; s++) cpa16(dst + s * 16, src + s * 8);
    };

    load_kv(0, 0); CPA_COMMIT();
    load_kv(1, 1); CPA_COMMIT();

    const int NKT = SEQ / 64;   // 32
    for (int kt = 0; kt < NKT; ++kt) {
        const int st = kt & 1;
        if (kt + 1 < NKT) asm volatile("cp.async.wait_group 1;" ::: "memory");
        else              asm volatile("cp.async.wait_group 0;" ::: "memory");
        __syncthreads();

        const uint32_t stb = sb + st * ASTG;

        // ---- S = Q K^T (3-term split), fp32 accum ----
        float sacc[8][4];
#pragma unroll
        for (int j = 0; j < 8; j++)
#pragma unroll
            for (int q = 0; q < 4; q++) sacc[j][q] = 0.0f;

#pragma unroll
        for (int c = 0; c < 4; c++) {        // hdim k-chunks
#pragma unroll
            for (int p = 0; p < 4; p++) {    // 16-key groups
                uint32_t kbh[4], kbl[4];
                uint32_t ka = stb + (uint32_t)(((p * 16 + rB) * AS + cB + c * 16) * 2);
                LDMX4(kbh, ka);
                LDMX4(kbl, ka + ATILE);
#pragma unroll
                for (int q = 0; q < 2; q++) {
                    const int nt = 2 * p + q;
                    mma16816(sacc[nt], qfh[c], kbh[2 * q], kbh[2 * q + 1]);
                    mma16816(sacc[nt], qfh[c], kbl[2 * q], kbl[2 * q + 1]);
                    mma16816(sacc[nt], qfl[c], kbh[2 * q], kbh[2 * q + 1]);
                }
            }
        }

        // ---- online softmax (rows l>>2 and l>>2+8 of this warp) ----
        float mnew0 = mrow0, mnew1 = mrow1;
#pragma unroll
        for (int j = 0; j < 8; j++) {
            sacc[j][0] *= 0.125f; sacc[j][1] *= 0.125f;
            sacc[j][2] *= 0.125f; sacc[j][3] *= 0.125f;
            mnew0 = fmaxf(mnew0, fmaxf(sacc[j][0], sacc[j][1]));
            mnew1 = fmaxf(mnew1, fmaxf(sacc[j][2], sacc[j][3]));
        }
        mnew0 = fmaxf(mnew0, __shfl_xor_sync(0xffffffffu, mnew0, 1));
        mnew0 = fmaxf(mnew0, __shfl_xor_sync(0xffffffffu, mnew0, 2));
        mnew1 = fmaxf(mnew1, __shfl_xor_sync(0xffffffffu, mnew1, 1));
        mnew1 = fmaxf(mnew1, __shfl_xor_sync(0xffffffffu, mnew1, 2));
        const float corr0 = __expf(mrow0 - mnew0);
        const float corr1 = __expf(mrow1 - mnew1);
        mrow0 = mnew0; mrow1 = mnew1;

        uint32_t ph0[8], ph1[8], pl0[8], pl1[8];
        float ts0 = 0.0f, ts1 = 0.0f;
#pragma unroll
        for (int j = 0; j < 8; j++) {
            float p00 = __expf(sacc[j][0] - mnew0);
            float p01 = __expf(sacc[j][1] - mnew0);
            float p10 = __expf(sacc[j][2] - mnew1);
            float p11 = __expf(sacc[j][3] - mnew1);
            ts0 += p00 + p01; ts1 += p10 + p11;
            uint32_t u;
            PKBF2(u, p00, p01); ph0[j] = u;
            float r0 = p00 - __uint_as_float(u << 16);
            float r1 = p01 - __uint_as_float(u & 0xffff0000u);
            PKBF2(u, r0, r1);  pl0[j] = u;
            PKBF2(u, p10, p11); ph1[j] = u;
            r0 = p10 - __uint_as_float(u << 16);
            r1 = p11 - __uint_as_float(u & 0xffff0000u);
            PKBF2(u, r0, r1);  pl1[j] = u;
        }
        // row sum lives across the 4 lanes of the quad -> reduce (R8 bug: missing)
        ts0 += __shfl_xor_sync(0xffffffffu, ts0, 1);
        ts0 += __shfl_xor_sync(0xffffffffu, ts0, 2);
        ts1 += __shfl_xor_sync(0xffffffffu, ts1, 1);
        ts1 += __shfl_xor_sync(0xffffffffu, ts1, 2);
        lrow0 = lrow0 * corr0 + ts0;
        lrow1 = lrow1 * corr1 + ts1;
#pragma unroll
        for (int j = 0; j < 8; j++) {
            oacc[j][0] *= corr0; oacc[j][1] *= corr0;
            oacc[j][2] *= corr1; oacc[j][3] *= corr1;
        }

        // ---- O += P V (3-term), V^T via ldmatrix.trans ----
#pragma unroll
        for (int kk = 0; kk < 4; kk++) {     // 16-key chunks
            uint32_t pah[4] = { ph0[2 * kk], ph1[2 * kk], ph0[2 * kk + 1], ph1[2 * kk + 1] };
            uint32_t pal[4] = { pl0[2 * kk], pl1[2 * kk], pl0[2 * kk + 1], pl1[2 * kk + 1] };
#pragma unroll
            for (int p = 0; p < 4; p++) {    // 16-hdim pairs
                uint32_t vbh[4], vbl[4];
                uint32_t va = stb + 2 * ATILE +
                              (uint32_t)(((kk * 16 + rA) * AS + cA + p * 16) * 2);
                LDMT4(vbh, va);
                LDMT4(vbl, va + ATILE);
#pragma unroll
                for (int q = 0; q < 2; q++) {
                    const int nt = 2 * p + q;
                    mma16816(oacc[nt], pah, vbh[2 * q], vbh[2 * q + 1]);
                    mma16816(oacc[nt], pah, vbl[2 * q], vbl[2 * q + 1]);
                    mma16816(oacc[nt], pal, vbh[2 * q], vbh[2 * q + 1]);
                }
            }
        }

        __syncthreads();
        if (kt + 2 < NKT) { load_kv(kt + 2, st); CPA_COMMIT(); }
    }

    // ---- finalize: O / l, write [token][h*64 + d] fp32 ----
    const float inv0 = 1.0f / lrow0;
    const float inv1 = 1.0f / lrow1;
    const size_t t0 = tok0 + wid * 16 + (lane >> 2);
    float* o0 = out + t0 * CM + h * HDIM + (lane & 3) * 2;
    float* o1 = o0 + (size_t)8 * CM;
#pragma unroll
    for (int j = 0; j < 8; j++) {
        *(float2*)(o0 + j * 8) = make_float2(oacc[j][0] * inv0, oacc[j][1] * inv0);
        *(float2*)(o1 + j * 8) = make_float2(oacc[j][2] * inv1, oacc[j][3] * inv1);
    }
}

// =============================================================================
// LayerNorm over last dim (1024). One block per row, 256 threads x float4.
// =============================================================================
__global__ __launch_bounds__(256)
void ln_k(const float* __restrict__ in, const float* __restrict__ gamma,
          const float* __restrict__ beta, float* __restrict__ out)
{
    const int row = blockIdx.x;
    const int tid = threadIdx.x;
    const float4 v = ((const float4*)(in + (size_t)row * CM))[tid];

    float s  = v.x + v.y + v.z + v.w;
    float ss = v.x * v.x + v.y * v.y + v.z * v.z + v.w * v.w;
#pragma unroll
    for (int o = 16; o > 0; o >>= 1) {
        s  += __shfl_xor_sync(0xffffffffu, s,  o);
        ss += __shfl_xor_sync(0xffffffffu, ss, o);
    }
    __shared__ float rs[8], rq[8];
    if ((tid & 31) == 0) { rs[tid >> 5] = s; rq[tid >> 5] = ss; }
    __syncthreads();
    float tot = 0.0f, totq = 0.0f;
#pragma unroll
    for (int i = 0; i < 8; i++) { tot += rs[i]; totq += rq[i]; }

    const float mean = tot * (1.0f / CM);
    const float var  = totq * (1.0f / CM) - mean * mean;
    const float inv  = rsqrtf(var + 1e-5f);

    const float4 g4 = ((const float4*)gamma)[tid];
    const float4 b4 = ((const float4*)beta)[tid];
    float4 o;
    o.x = (v.x - mean) * inv * g4.x + b4.x;
    o.y = (v.y - mean) * inv * g4.y + b4.y;
    o.z = (v.z - mean) * inv * g4.z + b4.z;
    o.w = (v.w - mean) * inv * g4.w + b4.w;
    ((float4*)(out + (size_t)row * CM))[tid] = o;
}

// =============================================================================
// launch
// =============================================================================
static inline void cvt(const float* x, __nv_bfloat16* hi, __nv_bfloat16* lo, size_t n) {
    int n4 = (int)(n / 4);
    cvt_hilo<<<(n4 + 255) / 256, 256>>>(x, hi, lo, n4);
}

extern "C" void kernel_launch(void* const* d_in, const int* in_sizes, int n_in,
                              void* d_out, int out_size)
{
    (void)in_sizes; (void)n_in; (void)out_size;
    const float* src   = (const float*)d_in[0];
    const float* wqkv  = (const float*)d_in[1];
    const float* wproj = (const float*)d_in[2];
    const float* bproj = (const float*)d_in[3];
    const float* w1    = (const float*)d_in[4];
    const float* b1    = (const float*)d_in[5];
    const float* w2    = (const float*)d_in[6];
    const float* b2    = (const float*)d_in[7];
    const float* g1    = (const float*)d_in[8];
    const float* be1   = (const float*)d_in[9];
    const float* g2    = (const float*)d_in[10];
    const float* be2   = (const float*)d_in[11];
    float* out = (float*)d_out;

    float *qkv, *attn, *res, *x, *ff;
    __nv_bfloat16 *ah, *al, *bh, *bl;
    cudaGetSymbolAddress((void**)&qkv,  g_qkv);
    cudaGetSymbolAddress((void**)&attn, g_attn);
    cudaGetSymbolAddress((void**)&res,  g_res);
    cudaGetSymbolAddress((void**)&x,    g_x);
    cudaGetSymbolAddress((void**)&ff,   g_ff);
    cudaGetSymbolAddress((void**)&ah,   g_ah);
    cudaGetSymbolAddress((void**)&al,   g_al);
    cudaGetSymbolAddress((void**)&bh,   g_bh);
    cudaGetSymbolAddress((void**)&bl,   g_bl);

    cudaFuncSetAttribute(gemm_mma<0>, cudaFuncAttributeMaxDynamicSharedMemorySize, GEMM_SMEM);
    cudaFuncSetAttribute(gemm_mma<1>, cudaFuncAttributeMaxDynamicSharedMemorySize, GEMM_SMEM);
    cudaFuncSetAttribute(attn_mma,    cudaFuncAttributeMaxDynamicSharedMemorySize, ATTN_SMEM);

    // 1) QKV projection: [4096,1024] x [3072,1024]^T -> [4096,3072]
    cvt(src,  ah, al, (size_t)MTOT * CM);
    cvt(wqkv, bh, bl, (size_t)3 * CM * CM);
    gemm_mma<0><<<dim3(3 * CM / 128, MTOT / 128), 256, GEMM_SMEM>>>(
        ah, al, bh, bl, nullptr, nullptr, qkv, MTOT, 3 * CM, CM);

    // 2) tensor-core flash attention on split-bf16 qkv
    cvt(qkv, ah, al, (size_t)MTOT * 3 * CM);
    attn_mma<<<dim3(SEQ / 128, NHEAD, NB), 256, ATTN_SMEM>>>(ah, al, attn);

    // 3) output projection + bias + residual(src)
    cvt(attn,  ah, al, (size_t)MTOT * CM);
    cvt(wproj, bh, bl, (size_t)CM * CM);
    gemm_mma<0><<<dim3(CM / 128, MTOT / 128), 256, GEMM_SMEM>>>(
        ah, al, bh, bl, bproj, src, res, MTOT, CM, CM);

    // 4) LayerNorm 1
    ln_k<<<MTOT, 256>>>(res, g1, be1, x);

    // 5) FFN up: relu(x @ w1^T + b1) -> [4096,4096]
    cvt(x,  ah, al, (size_t)MTOT * CM);
    cvt(w1, bh, bl, (size_t)FF * CM);
    gemm_mma<1><<<dim3(FF / 128, MTOT / 128), 256, GEMM_SMEM>>>(
        ah, al, bh, bl, b1, nullptr, ff, MTOT, FF, CM);

    // 6) FFN down + bias + residual(x)
    cvt(ff, ah, al, (size_t)MTOT * FF);
    cvt(w2, bh, bl, (size_t)CM * FF);
    gemm_mma<0><<<dim3(CM / 128, MTOT / 128), 256, GEMM_SMEM>>>(
        ah, al, bh, bl, b2, x, res, MTOT, CM, FF);

    // 7) LayerNorm 2 -> output
    ln_k<<<MTOT, 256>>>(res, g2, be2, out);
}

// round 10
// speedup vs baseline: 2.9764x; 1.0117x over previous
#include <cuda_runtime.h>
#include <cuda_bf16.h>
#include <cstdint>

typedef unsigned long long ull;

#define SEQ   2048
#define NB    2
#define CM    1024
#define NHEAD 16
#define HDIM  64
#define FF    4096
#define MTOT  (NB*SEQ)   // 4096 rows total

// ---------------- scratch (static device globals; no allocation) -------------
__device__ float g_qkv[(size_t)MTOT * 3 * CM];   // 50 MB (reused as bf16 hi buffers)
__device__ float g_res[(size_t)MTOT * CM];       // 16 MB
__device__ float g_x[(size_t)MTOT * CM];         // 16 MB
__device__ float g_ff[(size_t)MTOT * FF];        // 64 MB (reused as bf16 lo buffers)
// bf16 hi/lo staging
__device__ __nv_bfloat16 g_ah[(size_t)MTOT * CM];  //  8 MB (A-side hi)
__device__ __nv_bfloat16 g_al[(size_t)MTOT * CM];  //  8 MB (A-side lo)
__device__ __nv_bfloat16 g_bh[(size_t)FF * CM];    //  8 MB (B-side hi)
__device__ __nv_bfloat16 g_bl[(size_t)FF * CM];    //  8 MB (B-side lo)

// ---------------- mma.sync / ldmatrix / cp.async primitives -----------------
__device__ __forceinline__ uint32_t smem_u32(const void* p) {
    uint32_t a;
    asm("{ .reg .u64 t; cvta.to.shared.u64 t, %1; cvt.u32.u64 %0, t; }" : "=r"(a) : "l"(p));
    return a;
}
__device__ __forceinline__ void cpa16(uint32_t dst, const void* src) {
    asm volatile("cp.async.cg.shared.global [%0], [%1], 16;" :: "r"(dst), "l"(src));
}
#define CPA_COMMIT() asm volatile("cp.async.commit_group;" ::: "memory")

#define LDMX4(d, a) \
    asm volatile("ldmatrix.sync.aligned.m8n8.x4.shared.b16 {%0,%1,%2,%3}, [%4];" \
        : "=r"((d)[0]), "=r"((d)[1]), "=r"((d)[2]), "=r"((d)[3]) : "r"(a))
#define LDMT4(d, a) \
    asm volatile("ldmatrix.sync.aligned.m8n8.x4.trans.shared.b16 {%0,%1,%2,%3}, [%4];" \
        : "=r"((d)[0]), "=r"((d)[1]), "=r"((d)[2]), "=r"((d)[3]) : "r"(a))

__device__ __forceinline__ void mma16816(float* d, const uint32_t* a,
                                         uint32_t b0, uint32_t b1) {
    asm volatile(
        "mma.sync.aligned.m16n8k16.row.col.f32.bf16.bf16.f32 "
        "{%0,%1,%2,%3}, {%4,%5,%6,%7}, {%8,%9}, {%0,%1,%2,%3};"
        : "+f"(d[0]), "+f"(d[1]), "+f"(d[2]), "+f"(d[3])
        : "r"(a[0]), "r"(a[1]), "r"(a[2]), "r"(a[3]), "r"(b0), "r"(b1));
}

// pack two fp32 into bf16x2: u.lo = first arg, u.hi = second arg
#define PKBF2(u, lo, hi) \
    asm("cvt.rn.bf16x2.f32 %0, %1, %2;" : "=r"(u) : "f"(hi), "f"(lo))

// split a float2 into hi bf16x2 + lo-residual bf16x2
__device__ __forceinline__ void split2(float2 o, uint32_t& uh, uint32_t& ul) {
    PKBF2(uh, o.x, o.y);
    float rx = o.x - __uint_as_float(uh << 16);
    float ry = o.y - __uint_as_float(uh & 0xffff0000u);
    PKBF2(ul, rx, ry);
}

// =============================================================================
// fp32 -> (bf16 hi, bf16 lo) split conversion (src + weights only)
// =============================================================================
__global__ __launch_bounds__(256)
void cvt_hilo(const float* __restrict__ x, __nv_bfloat16* __restrict__ hi,
              __nv_bfloat16* __restrict__ lo, int n4)
{
    int i = blockIdx.x * blockDim.x + threadIdx.x;
    if (i >= n4) return;
    float4 v = ((const float4*)x)[i];
    uint32_t u0, l0, u1, l1;
    split2(make_float2(v.x, v.y), u0, l0);
    split2(make_float2(v.z, v.w), u1, l1);
    uint32_t* hp = (uint32_t*)(hi + 4 * (size_t)i);
    uint32_t* lp = (uint32_t*)(lo + 4 * (size_t)i);
    hp[0] = u0; hp[1] = u1;
    lp[0] = l0; lp[1] = l1;
}

// =============================================================================
// mma.sync GEMM: C[M,N] = A[M,K] * B[N,K]^T   (split-bf16: AhBh + AhBl + AlBh)
// Block: 128x128x32, 256 threads = 8 warps (2 x 4), warp tile 64x32.
// 3-stage cp.async pipeline, loads front-issued, one barrier per chunk.
// Epilogue: bias -> relu -> residual -> {fp32 C | bf16 hi/lo C}.
// =============================================================================
#define GS   40
#define GTILE (128 * GS * 2)
#define GSTG  (4 * GTILE)            // 40960 B per stage
#define GEMM_SMEM (3 * GSTG)         // 122880 B

template <int RELU>
__global__ __launch_bounds__(256, 1)
void gemm_mma(const __nv_bfloat16* __restrict__ Ah, const __nv_bfloat16* __restrict__ Al,
              const __nv_bfloat16* __restrict__ Bh, const __nv_bfloat16* __restrict__ Bl,
              const float* __restrict__ bias, const float* __restrict__ add,
              float* __restrict__ Cf,
              __nv_bfloat16* __restrict__ Chi, __nv_bfloat16* __restrict__ Clo,
              int M, int N, int K)
{
    extern __shared__ char smem[];
    const uint32_t sb = smem_u32(smem);
    const int tid  = threadIdx.x;
    const int lane = tid & 31;
    const int wid  = tid >> 5;
    const int wm   = wid & 1;
    const int wn   = wid >> 1;
    const int m0   = blockIdx.y * 128;
    const int n0   = blockIdx.x * 128;
    const int nch  = K >> 5;

    const int grp = lane >> 3;
    const int rA  = (lane & 7) + ((grp & 1) << 3);
    const int cA  = (grp >> 1) << 3;
    const int rB  = (lane & 7) + ((grp >> 1) << 3);
    const int cB  = (grp & 1) << 3;

    float acc[4][4][4];
#pragma unroll
    for (int i = 0; i < 4; i++)
#pragma unroll
        for (int j = 0; j < 4; j++)
#pragma unroll
            for (int q = 0; q < 4; q++) acc[i][j][q] = 0.0f;

    auto load_chunk = [&](int kc, int st) {
        const uint32_t base = sb + st * GSTG;
        const int k0 = kc << 5;
#pragma unroll
        for (int h = 0; h < 2; h++) {
            int u   = tid + h * 256;
            int row = u >> 2, seg = u & 3;
            uint32_t doff = (uint32_t)(row * (GS * 2) + seg * 16);
            size_t ga = (size_t)(m0 + row) * K + k0 + seg * 8;
            size_t gb = (size_t)(n0 + row) * K + k0 + seg * 8;
            cpa16(base + 0 * GTILE + doff, Ah + ga);
            cpa16(base + 1 * GTILE + doff, Al + ga);
            cpa16(base + 2 * GTILE + doff, Bh + gb);
            cpa16(base + 3 * GTILE + doff, Bl + gb);
        }
    };

    load_chunk(0, 0); CPA_COMMIT();
    load_chunk(1, 1); CPA_COMMIT();

    const uint32_t laneA = (uint32_t)((rA * GS + cA) * 2);
    const uint32_t laneB = (uint32_t)((rB * GS + cB) * 2);

    for (int c = 0; c < nch; ++c) {
        if (c + 1 < nch) asm volatile("cp.async.wait_group 1;" ::: "memory");
        else             asm volatile("cp.async.wait_group 0;" ::: "memory");
        __syncthreads();
        // front-issue load for chunk c+2 into the stage freed by chunk c-1
        if (c + 2 < nch) { load_chunk(c + 2, (c + 2) % 3); CPA_COMMIT(); }

        const uint32_t stb = sb + (c % 3) * GSTG;
        const uint32_t aH = stb + 0 * GTILE + (uint32_t)(wm * 64 * GS * 2) + laneA;
        const uint32_t aL = stb + 1 * GTILE + (uint32_t)(wm * 64 * GS * 2) + laneA;
        const uint32_t bH = stb + 2 * GTILE + (uint32_t)(wn * 32 * GS * 2) + laneB;
        const uint32_t bL = stb + 3 * GTILE + (uint32_t)(wn * 32 * GS * 2) + laneB;

#pragma unroll
        for (int ks = 0; ks < 2; ks++) {
            const uint32_t ko = (uint32_t)(ks * 16 * 2);
            uint32_t fah[4][4], fal[4][4], fbh[2][4], fbl[2][4];
#pragma unroll
            for (int mt = 0; mt < 4; mt++) {
                LDMX4(fah[mt], aH + (uint32_t)(mt * 16 * GS * 2) + ko);
                LDMX4(fal[mt], aL + (uint32_t)(mt * 16 * GS * 2) + ko);
            }
#pragma unroll
            for (int p = 0; p < 2; p++) {
                LDMX4(fbh[p], bH + (uint32_t)(p * 16 * GS * 2) + ko);
                LDMX4(fbl[p], bL + (uint32_t)(p * 16 * GS * 2) + ko);
            }
#pragma unroll
            for (int mt = 0; mt < 4; mt++) {
#pragma unroll
                for (int nt = 0; nt < 4; nt++) {
                    const int p = nt >> 1, q = nt & 1;
                    mma16816(acc[mt][nt], fah[mt], fbh[p][2 * q], fbh[p][2 * q + 1]);
                    mma16816(acc[mt][nt], fah[mt], fbl[p][2 * q], fbl[p][2 * q + 1]);
                    mma16816(acc[mt][nt], fal[mt], fbh[p][2 * q], fbh[p][2 * q + 1]);
                }
            }
        }
    }

    const int qr = lane >> 2;
    const int qc = (lane & 3) * 2;
    const bool hasb = (bias != nullptr);
    const bool hasa = (add  != nullptr);
#pragma unroll
    for (int nt = 0; nt < 4; nt++) {
        const int n = n0 + wn * 32 + nt * 8 + qc;
        float2 bb = make_float2(0.f, 0.f);
        if (hasb) bb = *(const float2*)(bias + n);
#pragma unroll
        for (int mt = 0; mt < 4; mt++) {
#pragma unroll
            for (int half = 0; half < 2; half++) {
                const int m = m0 + wm * 64 + mt * 16 + qr + half * 8;
                const size_t off = (size_t)m * N + n;
                float2 o = make_float2(acc[mt][nt][2 * half]     + bb.x,
                                       acc[mt][nt][2 * half + 1] + bb.y);
                if (RELU) { o.x = fmaxf(o.x, 0.f); o.y = fmaxf(o.y, 0.f); }
                if (hasa) {
                    float2 r = *(const float2*)(add + off);
                    o.x += r.x; o.y += r.y;
                }
                if (Cf) *(float2*)(Cf + off) = o;
                if (Chi) {
                    uint32_t uh, ul;
                    split2(o, uh, ul);
                    *(uint32_t*)(Chi + off) = uh;
                    *(uint32_t*)(Clo + off) = ul;
                }
            }
        }
    }
}

// =============================================================================
// Tensor-core flash attention (mma.sync bf16, split-precision 3-term)
// Block: one (b, h), 128 q rows. 256 threads = 8 warps x 16 q rows.
// 3-stage K/V pipeline, loads front-issued, one barrier per tile.
// Output written directly as bf16 hi/lo (feeds the proj GEMM's A operand).
// =============================================================================
#define AS    72
#define ATILE (64 * AS * 2)        // 9216 B per 64x64 bf16 tile
#define ASTG  (4 * ATILE)          // kh,kl,vh,vl = 36864 B per stage
#define ATTN_SMEM (3 * ASTG)       // 110592 B

__global__ __launch_bounds__(256, 1)
void attn_mma(const __nv_bfloat16* __restrict__ qh,
              const __nv_bfloat16* __restrict__ ql,
              __nv_bfloat16* __restrict__ oh,
              __nv_bfloat16* __restrict__ ol)
{
    extern __shared__ char smem[];
    const uint32_t sb = smem_u32(smem);
    const int tid  = threadIdx.x;
    const int lane = tid & 31;
    const int wid  = tid >> 5;
    const int b  = blockIdx.z;
    const int h  = blockIdx.y;
    const int qt = blockIdx.x;

    const int grp = lane >> 3;
    const int rA  = (lane & 7) + ((grp & 1) << 3);
    const int cA  = (grp >> 1) << 3;
    const int rB  = (lane & 7) + ((grp >> 1) << 3);
    const int cB  = (grp & 1) << 3;

    const size_t tok0 = (size_t)b * SEQ + (size_t)qt * 128;

    // ---- stage Q tile (128 x 64, hi+lo) into smem, build register frags ----
#pragma unroll
    for (int i = 0; i < 4; i++) {
        int u = tid + i * 256;
        int r = u >> 3, seg = u & 7;
        const __nv_bfloat16* sh = qh + (tok0 + r) * (3 * CM) + h * HDIM + seg * 8;
        const __nv_bfloat16* sl = ql + (tok0 + r) * (3 * CM) + h * HDIM + seg * 8;
        uint32_t d = (uint32_t)(r * (AS * 2) + seg * 16);
        cpa16(sb + d, sh);
        cpa16(sb + (uint32_t)ASTG + d, sl);
    }
    CPA_COMMIT();
    asm volatile("cp.async.wait_group 0;" ::: "memory");
    __syncthreads();

    uint32_t qfh[4][4], qfl[4][4];
#pragma unroll
    for (int c = 0; c < 4; c++) {
        uint32_t a = sb + (uint32_t)(((wid * 16 + rA) * AS + cA + c * 16) * 2);
        LDMX4(qfh[c], a);
        LDMX4(qfl[c], a + (uint32_t)ASTG);
    }
    __syncthreads();   // Q frags in regs; smem free for K/V pipeline

    float oacc[8][4];
#pragma unroll
    for (int j = 0; j < 8; j++)
#pragma unroll
        for (int q = 0; q < 4; q++) oacc[j][q] = 0.0f;
    float mrow0 = -1e30f, mrow1 = -1e30f, lrow0 = 0.0f, lrow1 = 0.0f;

    auto load_kv = [&](int kt, int st) {
        const int t = tid >> 6;          // 0=kh 1=kl 2=vh 3=vl
        const int r = tid & 63;
        size_t row = ((size_t)b * SEQ + kt * 64 + r) * (3 * CM) + h * HDIM;
        const __nv_bfloat16* src;
        if      (t == 0) src = qh + row + CM;
        else if (t == 1) src = ql + row + CM;
        else if (t == 2) src = qh + row + 2 * CM;
        else             src = ql + row + 2 * CM;
        uint32_t dst = sb + st * ASTG + t * ATILE + (uint32_t)(r * AS * 2);
#pragma unroll
        for (int s = 0; s < 8; s++) cpa16(dst + s * 16, src + s * 8);
    };

    load_kv(0, 0); CPA_COMMIT();
    load_kv(1, 1); CPA_COMMIT();

    const int NKT = SEQ / 64;   // 32
    for (int kt = 0; kt < NKT; ++kt) {
        if (kt + 1 < NKT) asm volatile("cp.async.wait_group 1;" ::: "memory");
        else              asm volatile("cp.async.wait_group 0;" ::: "memory");
        __syncthreads();
        if (kt + 2 < NKT) { load_kv(kt + 2, (kt + 2) % 3); CPA_COMMIT(); }

        const uint32_t stb = sb + (kt % 3) * ASTG;

        // ---- S = Q K^T (3-term split), fp32 accum ----
        float sacc[8][4];
#pragma unroll
        for (int j = 0; j < 8; j++)
#pragma unroll
            for (int q = 0; q < 4; q++) sacc[j][q] = 0.0f;

#pragma unroll
        for (int c = 0; c < 4; c++) {
#pragma unroll
            for (int p = 0; p < 4; p++) {
                uint32_t kbh[4], kbl[4];
                uint32_t ka = stb + (uint32_t)(((p * 16 + rB) * AS + cB + c * 16) * 2);
                LDMX4(kbh, ka);
                LDMX4(kbl, ka + ATILE);
#pragma unroll
                for (int q = 0; q < 2; q++) {
                    const int nt = 2 * p + q;
                    mma16816(sacc[nt], qfh[c], kbh[2 * q], kbh[2 * q + 1]);
                    mma16816(sacc[nt], qfh[c], kbl[2 * q], kbl[2 * q + 1]);
                    mma16816(sacc[nt], qfl[c], kbh[2 * q], kbh[2 * q + 1]);
                }
            }
        }

        // ---- online softmax (rows l>>2 and l>>2+8 of this warp) ----
        float mnew0 = mrow0, mnew1 = mrow1;
#pragma unroll
        for (int j = 0; j < 8; j++) {
            sacc[j][0] *= 0.125f; sacc[j][1] *= 0.125f;
            sacc[j][2] *= 0.125f; sacc[j][3] *= 0.125f;
            mnew0 = fmaxf(mnew0, fmaxf(sacc[j][0], sacc[j][1]));
            mnew1 = fmaxf(mnew1, fmaxf(sacc[j][2], sacc[j][3]));
        }
        mnew0 = fmaxf(mnew0, __shfl_xor_sync(0xffffffffu, mnew0, 1));
        mnew0 = fmaxf(mnew0, __shfl_xor_sync(0xffffffffu, mnew0, 2));
        mnew1 = fmaxf(mnew1, __shfl_xor_sync(0xffffffffu, mnew1, 1));
        mnew1 = fmaxf(mnew1, __shfl_xor_sync(0xffffffffu, mnew1, 2));
        const float corr0 = __expf(mrow0 - mnew0);
        const float corr1 = __expf(mrow1 - mnew1);
        mrow0 = mnew0; mrow1 = mnew1;

        uint32_t ph0[8], ph1[8], pl0[8], pl1[8];
        float ts0 = 0.0f, ts1 = 0.0f;
#pragma unroll
        for (int j = 0; j < 8; j++) {
            float p00 = __expf(sacc[j][0] - mnew0);
            float p01 = __expf(sacc[j][1] - mnew0);
            float p10 = __expf(sacc[j][2] - mnew1);
            float p11 = __expf(sacc[j][3] - mnew1);
            ts0 += p00 + p01; ts1 += p10 + p11;
            uint32_t u, ul;
            split2(make_float2(p00, p01), u, ul); ph0[j] = u; pl0[j] = ul;
            split2(make_float2(p10, p11), u, ul); ph1[j] = u; pl1[j] = ul;
        }
        ts0 += __shfl_xor_sync(0xffffffffu, ts0, 1);
        ts0 += __shfl_xor_sync(0xffffffffu, ts0, 2);
        ts1 += __shfl_xor_sync(0xffffffffu, ts1, 1);
        ts1 += __shfl_xor_sync(0xffffffffu, ts1, 2);
        lrow0 = lrow0 * corr0 + ts0;
        lrow1 = lrow1 * corr1 + ts1;
#pragma unroll
        for (int j = 0; j < 8; j++) {
            oacc[j][0] *= corr0; oacc[j][1] *= corr0;
            oacc[j][2] *= corr1; oacc[j][3] *= corr1;
        }

        // ---- O += P V (3-term), V^T via ldmatrix.trans ----
#pragma unroll
        for (int kk = 0; kk < 4; kk++) {
            uint32_t pah[4] = { ph0[2 * kk], ph1[2 * kk], ph0[2 * kk + 1], ph1[2 * kk + 1] };
            uint32_t pal[4] = { pl0[2 * kk], pl1[2 * kk], pl0[2 * kk + 1], pl1[2 * kk + 1] };
#pragma unroll
            for (int p = 0; p < 4; p++) {
                uint32_t vbh[4], vbl[4];
                uint32_t va = stb + 2 * ATILE +
                              (uint32_t)(((kk * 16 + rA) * AS + cA + p * 16) * 2);
                LDMT4(vbh, va);
                LDMT4(vbl, va + ATILE);
#pragma unroll
                for (int q = 0; q < 2; q++) {
                    const int nt = 2 * p + q;
                    mma16816(oacc[nt], pah, vbh[2 * q], vbh[2 * q + 1]);
                    mma16816(oacc[nt], pah, vbl[2 * q], vbl[2 * q + 1]);
                    mma16816(oacc[nt], pal, vbh[2 * q], vbh[2 * q + 1]);
                }
            }
        }
    }

    // ---- finalize: O / l, write bf16 hi/lo at [token][h*64 + d] ----
    const float inv0 = 1.0f / lrow0;
    const float inv1 = 1.0f / lrow1;
    const size_t t0 = tok0 + wid * 16 + (lane >> 2);
    const size_t base0 = t0 * CM + h * HDIM + (lane & 3) * 2;
    const size_t base1 = base0 + (size_t)8 * CM;
#pragma unroll
    for (int j = 0; j < 8; j++) {
        uint32_t uh, ul;
        split2(make_float2(oacc[j][0] * inv0, oacc[j][1] * inv0), uh, ul);
        *(uint32_t*)(oh + base0 + j * 8) = uh;
        *(uint32_t*)(ol + base0 + j * 8) = ul;
        split2(make_float2(oacc[j][2] * inv1, oacc[j][3] * inv1), uh, ul);
        *(uint32_t*)(oh + base1 + j * 8) = uh;
        *(uint32_t*)(ol + base1 + j * 8) = ul;
    }
}

// =============================================================================
// LayerNorm over last dim (1024). One block per row, 256 threads x float4.
// Optionally also emits bf16 hi/lo split of the output.
// =============================================================================
__global__ __launch_bounds__(256)
void ln_k(const float* __restrict__ in, const float* __restrict__ gamma,
          const float* __restrict__ beta, float* __restrict__ out,
          __nv_bfloat16* __restrict__ ohi, __nv_bfloat16* __restrict__ olo)
{
    const int row = blockIdx.x;
    const int tid = threadIdx.x;
    const float4 v = ((const float4*)(in + (size_t)row * CM))[tid];

    float s  = v.x + v.y + v.z + v.w;
    float ss = v.x * v.x + v.y * v.y + v.z * v.z + v.w * v.w;
#pragma unroll
    for (int o = 16; o > 0; o >>= 1) {
        s  += __shfl_xor_sync(0xffffffffu, s,  o);
        ss += __shfl_xor_sync(0xffffffffu, ss, o);
    }
    __shared__ float rs[8], rq[8];
    if ((tid & 31) == 0) { rs[tid >> 5] = s; rq[tid >> 5] = ss; }
    __syncthreads();
    float tot = 0.0f, totq = 0.0f;
#pragma unroll
    for (int i = 0; i < 8; i++) { tot += rs[i]; totq += rq[i]; }

    const float mean = tot * (1.0f / CM);
    const float var  = totq * (1.0f / CM) - mean * mean;
    const float inv  = rsqrtf(var + 1e-5f);

    const float4 g4 = ((const float4*)gamma)[tid];
    const float4 b4 = ((const float4*)beta)[tid];
    float4 o;
    o.x = (v.x - mean) * inv * g4.x + b4.x;
    o.y = (v.y - mean) * inv * g4.y + b4.y;
    o.z = (v.z - mean) * inv * g4.z + b4.z;
    o.w = (v.w - mean) * inv * g4.w + b4.w;
    ((float4*)(out + (size_t)row * CM))[tid] = o;

    if (ohi) {
        uint32_t u0, l0, u1, l1;
        split2(make_float2(o.x, o.y), u0, l0);
        split2(make_float2(o.z, o.w), u1, l1);
        uint32_t* hp = (uint32_t*)(ohi + (size_t)row * CM + tid * 4);
        uint32_t* lp = (uint32_t*)(olo + (size_t)row * CM + tid * 4);
        hp[0] = u0; hp[1] = u1;
        lp[0] = l0; lp[1] = l1;
    }
}

// =============================================================================
// launch
// =============================================================================
static inline void cvt(const float* x, __nv_bfloat16* hi, __nv_bfloat16* lo, size_t n) {
    int n4 = (int)(n / 4);
    cvt_hilo<<<(n4 + 255) / 256, 256>>>(x, hi, lo, n4);
}

extern "C" void kernel_launch(void* const* d_in, const int* in_sizes, int n_in,
                              void* d_out, int out_size)
{
    (void)in_sizes; (void)n_in; (void)out_size;
    const float* src   = (const float*)d_in[0];
    const float* wqkv  = (const float*)d_in[1];
    const float* wproj = (const float*)d_in[2];
    const float* bproj = (const float*)d_in[3];
    const float* w1    = (const float*)d_in[4];
    const float* b1    = (const float*)d_in[5];
    const float* w2    = (const float*)d_in[6];
    const float* b2    = (const float*)d_in[7];
    const float* g1    = (const float*)d_in[8];
    const float* be1   = (const float*)d_in[9];
    const float* g2    = (const float*)d_in[10];
    const float* be2   = (const float*)d_in[11];
    float* out = (float*)d_out;

    float *qkvf, *res, *x, *fff;
    __nv_bfloat16 *ah, *al, *bh, *bl;
    cudaGetSymbolAddress((void**)&qkvf, g_qkv);
    cudaGetSymbolAddress((void**)&res,  g_res);
    cudaGetSymbolAddress((void**)&x,    g_x);
    cudaGetSymbolAddress((void**)&fff,  g_ff);
    cudaGetSymbolAddress((void**)&ah,   g_ah);
    cudaGetSymbolAddress((void**)&al,   g_al);
    cudaGetSymbolAddress((void**)&bh,   g_bh);
    cudaGetSymbolAddress((void**)&bl,   g_bl);

    // bf16 reinterpretations of the big fp32 scratch buffers
    __nv_bfloat16* qh  = (__nv_bfloat16*)qkvf;  // 12M bf16 = 24MB in 50MB
    __nv_bfloat16* ql  = (__nv_bfloat16*)fff;   // 12M bf16 = 24MB in 64MB
    __nv_bfloat16* ffh = (__nv_bfloat16*)qkvf;  // 16M bf16 = 32MB in 50MB
    __nv_bfloat16* ffl = (__nv_bfloat16*)fff;   // 16M bf16 = 32MB in 64MB

    cudaFuncSetAttribute(gemm_mma<0>, cudaFuncAttributeMaxDynamicSharedMemorySize, GEMM_SMEM);
    cudaFuncSetAttribute(gemm_mma<1>, cudaFuncAttributeMaxDynamicSharedMemorySize, GEMM_SMEM);
    cudaFuncSetAttribute(attn_mma,    cudaFuncAttributeMaxDynamicSharedMemorySize, ATTN_SMEM);

    // 1) QKV projection -> bf16 hi/lo directly (no fp32 qkv, no cvt pass)
    cvt(src,  ah, al, (size_t)MTOT * CM);
    cvt(wqkv, bh, bl, (size_t)3 * CM * CM);
    gemm_mma<0><<<dim3(3 * CM / 128, MTOT / 128), 256, GEMM_SMEM>>>(
        ah, al, bh, bl, nullptr, nullptr, nullptr, qh, ql, MTOT, 3 * CM, CM);

    // 2) flash attention -> bf16 hi/lo attn output (A operand of proj GEMM)
    attn_mma<<<dim3(SEQ / 128, NHEAD, NB), 256, ATTN_SMEM>>>(qh, ql, ah, al);

    // 3) output projection + bias + residual(src) -> fp32 res
    cvt(wproj, bh, bl, (size_t)CM * CM);
    gemm_mma<0><<<dim3(CM / 128, MTOT / 128), 256, GEMM_SMEM>>>(
        ah, al, bh, bl, bproj, src, res, nullptr, nullptr, MTOT, CM, CM);

    // 4) LayerNorm 1 -> fp32 x (residual for step 6) + bf16 hi/lo (A of FFN1)
    ln_k<<<MTOT, 256>>>(res, g1, be1, x, ah, al);

    // 5) FFN up: relu(x @ w1^T + b1) -> bf16 hi/lo directly
    cvt(w1, bh, bl, (size_t)FF * CM);
    gemm_mma<1><<<dim3(FF / 128, MTOT / 128), 256, GEMM_SMEM>>>(
        ah, al, bh, bl, b1, nullptr, nullptr, ffh, ffl, MTOT, FF, CM);

    // 6) FFN down + bias + residual(x) -> fp32 res
    cvt(w2, bh, bl, (size_t)CM * FF);
    gemm_mma<0><<<dim3(CM / 128, MTOT / 128), 256, GEMM_SMEM>>>(
        ffh, ffl, bh, bl, b2, x, res, nullptr, nullptr, MTOT, CM, FF);

    // 7) LayerNorm 2 -> output
    ln_k<<<MTOT, 256>>>(res, g2, be2, out, nullptr, nullptr);
}

// round 11
// speedup vs baseline: 3.0788x; 1.0344x over previous
#include <cuda_runtime.h>
#include <cuda_bf16.h>
#include <cstdint>

typedef unsigned long long ull;

#define SEQ   2048
#define NB    2
#define CM    1024
#define NHEAD 16
#define HDIM  64
#define FF    4096
#define MTOT  (NB*SEQ)   // 4096 rows total

// ---------------- scratch (static device globals; no allocation) -------------
__device__ float g_qkv[(size_t)MTOT * 3 * CM];   // 50 MB (reused as bf16 hi buffers)
__device__ float g_res[(size_t)MTOT * CM];       // 16 MB
__device__ float g_x[(size_t)MTOT * CM];         // 16 MB
__device__ float g_ff[(size_t)MTOT * FF];        // 64 MB (reused as bf16 lo buffers)
__device__ __nv_bfloat16 g_ah[(size_t)MTOT * CM];  //  8 MB (A-side hi)
__device__ __nv_bfloat16 g_al[(size_t)MTOT * CM];  //  8 MB (A-side lo)
__device__ __nv_bfloat16 g_bh[(size_t)FF * CM];    //  8 MB (B-side hi)
__device__ __nv_bfloat16 g_bl[(size_t)FF * CM];    //  8 MB (B-side lo)

// ---------------- mma.sync / ldmatrix / cp.async primitives -----------------
__device__ __forceinline__ uint32_t smem_u32(const void* p) {
    uint32_t a;
    asm("{ .reg .u64 t; cvta.to.shared.u64 t, %1; cvt.u32.u64 %0, t; }" : "=r"(a) : "l"(p));
    return a;
}
__device__ __forceinline__ void cpa16(uint32_t dst, const void* src) {
    asm volatile("cp.async.cg.shared.global [%0], [%1], 16;" :: "r"(dst), "l"(src));
}
#define CPA_COMMIT() asm volatile("cp.async.commit_group;" ::: "memory")

#define LDMX4(d, a) \
    asm volatile("ldmatrix.sync.aligned.m8n8.x4.shared.b16 {%0,%1,%2,%3}, [%4];" \
        : "=r"((d)[0]), "=r"((d)[1]), "=r"((d)[2]), "=r"((d)[3]) : "r"(a))
#define LDMT4(d, a) \
    asm volatile("ldmatrix.sync.aligned.m8n8.x4.trans.shared.b16 {%0,%1,%2,%3}, [%4];" \
        : "=r"((d)[0]), "=r"((d)[1]), "=r"((d)[2]), "=r"((d)[3]) : "r"(a))

__device__ __forceinline__ void mma16816(float* d, const uint32_t* a,
                                         uint32_t b0, uint32_t b1) {
    asm volatile(
        "mma.sync.aligned.m16n8k16.row.col.f32.bf16.bf16.f32 "
        "{%0,%1,%2,%3}, {%4,%5,%6,%7}, {%8,%9}, {%0,%1,%2,%3};"
        : "+f"(d[0]), "+f"(d[1]), "+f"(d[2]), "+f"(d[3])
        : "r"(a[0]), "r"(a[1]), "r"(a[2]), "r"(a[3]), "r"(b0), "r"(b1));
}

#define PKBF2(u, lo, hi) \
    asm("cvt.rn.bf16x2.f32 %0, %1, %2;" : "=r"(u) : "f"(hi), "f"(lo))

__device__ __forceinline__ void split2(float2 o, uint32_t& uh, uint32_t& ul) {
    PKBF2(uh, o.x, o.y);
    float rx = o.x - __uint_as_float(uh << 16);
    float ry = o.y - __uint_as_float(uh & 0xffff0000u);
    PKBF2(ul, rx, ry);
}

// =============================================================================
// fp32 -> (bf16 hi, bf16 lo) split conversion (src + weights only)
// =============================================================================
__global__ __launch_bounds__(256)
void cvt_hilo(const float* __restrict__ x, __nv_bfloat16* __restrict__ hi,
              __nv_bfloat16* __restrict__ lo, int n4)
{
    int i = blockIdx.x * blockDim.x + threadIdx.x;
    if (i >= n4) return;
    float4 v = ((const float4*)x)[i];
    uint32_t u0, l0, u1, l1;
    split2(make_float2(v.x, v.y), u0, l0);
    split2(make_float2(v.z, v.w), u1, l1);
    uint32_t* hp = (uint32_t*)(hi + 4 * (size_t)i);
    uint32_t* lp = (uint32_t*)(lo + 4 * (size_t)i);
    hp[0] = u0; hp[1] = u1;
    lp[0] = l0; lp[1] = l1;
}

// =============================================================================
// mma.sync GEMM: C[M,N] = A[M,K] * B[N,K]^T   (split-bf16: AhBh + AhBl + AlBh)
// Block: 128x256x32, 256 threads = 8 warps (2 M x 4 N), warp tile 64x64.
// MMA:LDSM ratio 6 (tensor-bound). 3-stage cp.async pipeline, front-issued.
// =============================================================================
#define GS      40
#define GTILE_A (128 * GS * 2)           // 10240 B
#define GTILE_B (256 * GS * 2)           // 20480 B
#define OFF_AH  0
#define OFF_AL  GTILE_A
#define OFF_BH  (2 * GTILE_A)
#define OFF_BL  (2 * GTILE_A + GTILE_B)
#define GSTG    (2 * GTILE_A + 2 * GTILE_B)   // 61440 B
#define GEMM_SMEM (3 * GSTG)                  // 184320 B

template <int RELU>
__global__ __launch_bounds__(256, 1)
void gemm_mma(const __nv_bfloat16* __restrict__ Ah, const __nv_bfloat16* __restrict__ Al,
              const __nv_bfloat16* __restrict__ Bh, const __nv_bfloat16* __restrict__ Bl,
              const float* __restrict__ bias, const float* __restrict__ add,
              float* __restrict__ Cf,
              __nv_bfloat16* __restrict__ Chi, __nv_bfloat16* __restrict__ Clo,
              int M, int N, int K)
{
    extern __shared__ char smem[];
    const uint32_t sb = smem_u32(smem);
    const int tid  = threadIdx.x;
    const int lane = tid & 31;
    const int wid  = tid >> 5;
    const int wm   = wid & 1;        // 2 warps along M (64 rows each)
    const int wn   = wid >> 1;       // 4 warps along N (64 cols each)
    const int m0   = blockIdx.y * 128;
    const int n0   = blockIdx.x * 256;
    const int nch  = K >> 5;

    const int grp = lane >> 3;
    const int rA  = (lane & 7) + ((grp & 1) << 3);
    const int cA  = (grp >> 1) << 3;
    const int rB  = (lane & 7) + ((grp >> 1) << 3);
    const int cB  = (grp & 1) << 3;

    float acc[4][8][4];
#pragma unroll
    for (int i = 0; i < 4; i++)
#pragma unroll
        for (int j = 0; j < 8; j++)
#pragma unroll
            for (int q = 0; q < 4; q++) acc[i][j][q] = 0.0f;

    auto load_chunk = [&](int kc, int st) {
        const uint32_t base = sb + st * GSTG;
        const int k0 = kc << 5;
#pragma unroll
        for (int h = 0; h < 2; h++) {            // A: 512 units per array
            int u   = tid + h * 256;
            int row = u >> 2, seg = u & 3;
            uint32_t doff = (uint32_t)(row * (GS * 2) + seg * 16);
            size_t ga = (size_t)(m0 + row) * K + k0 + seg * 8;
            cpa16(base + OFF_AH + doff, Ah + ga);
            cpa16(base + OFF_AL + doff, Al + ga);
        }
#pragma unroll
        for (int h = 0; h < 4; h++) {            // B: 1024 units per array
            int u   = tid + h * 256;
            int row = u >> 2, seg = u & 3;
            uint32_t doff = (uint32_t)(row * (GS * 2) + seg * 16);
            size_t gb = (size_t)(n0 + row) * K + k0 + seg * 8;
            cpa16(base + OFF_BH + doff, Bh + gb);
            cpa16(base + OFF_BL + doff, Bl + gb);
        }
    };

    load_chunk(0, 0); CPA_COMMIT();
    load_chunk(1, 1); CPA_COMMIT();

    const uint32_t laneA = (uint32_t)((rA * GS + cA) * 2);
    const uint32_t laneB = (uint32_t)((rB * GS + cB) * 2);

    for (int c = 0; c < nch; ++c) {
        if (c + 1 < nch) asm volatile("cp.async.wait_group 1;" ::: "memory");
        else             asm volatile("cp.async.wait_group 0;" ::: "memory");
        __syncthreads();
        if (c + 2 < nch) { load_chunk(c + 2, (c + 2) % 3); CPA_COMMIT(); }

        const uint32_t stb = sb + (c % 3) * GSTG;
        const uint32_t aH = stb + OFF_AH + (uint32_t)(wm * 64 * GS * 2) + laneA;
        const uint32_t aL = stb + OFF_AL + (uint32_t)(wm * 64 * GS * 2) + laneA;
        const uint32_t bH = stb + OFF_BH + (uint32_t)(wn * 64 * GS * 2) + laneB;
        const uint32_t bL = stb + OFF_BL + (uint32_t)(wn * 64 * GS * 2) + laneB;

#pragma unroll
        for (int ks = 0; ks < 2; ks++) {
            const uint32_t ko = (uint32_t)(ks * 16 * 2);
            uint32_t fah[4][4], fal[4][4], fbh[4][4], fbl[4][4];
#pragma unroll
            for (int mt = 0; mt < 4; mt++) {
                LDMX4(fah[mt], aH + (uint32_t)(mt * 16 * GS * 2) + ko);
                LDMX4(fal[mt], aL + (uint32_t)(mt * 16 * GS * 2) + ko);
            }
#pragma unroll
            for (int p = 0; p < 4; p++) {
                LDMX4(fbh[p], bH + (uint32_t)(p * 16 * GS * 2) + ko);
                LDMX4(fbl[p], bL + (uint32_t)(p * 16 * GS * 2) + ko);
            }
#pragma unroll
            for (int mt = 0; mt < 4; mt++) {
#pragma unroll
                for (int nt = 0; nt < 8; nt++) {
                    const int p = nt >> 1, q = nt & 1;
                    mma16816(acc[mt][nt], fah[mt], fbh[p][2 * q], fbh[p][2 * q + 1]);
                    mma16816(acc[mt][nt], fah[mt], fbl[p][2 * q], fbl[p][2 * q + 1]);
                    mma16816(acc[mt][nt], fal[mt], fbh[p][2 * q], fbh[p][2 * q + 1]);
                }
            }
        }
    }

    const int qr = lane >> 2;
    const int qc = (lane & 3) * 2;
    const bool hasb = (bias != nullptr);
    const bool hasa = (add  != nullptr);
#pragma unroll
    for (int nt = 0; nt < 8; nt++) {
        const int n = n0 + wn * 64 + nt * 8 + qc;
        float2 bb = make_float2(0.f, 0.f);
        if (hasb) bb = *(const float2*)(bias + n);
#pragma unroll
        for (int mt = 0; mt < 4; mt++) {
#pragma unroll
            for (int half = 0; half < 2; half++) {
                const int m = m0 + wm * 64 + mt * 16 + qr + half * 8;
                const size_t off = (size_t)m * N + n;
                float2 o = make_float2(acc[mt][nt][2 * half]     + bb.x,
                                       acc[mt][nt][2 * half + 1] + bb.y);
                if (RELU) { o.x = fmaxf(o.x, 0.f); o.y = fmaxf(o.y, 0.f); }
                if (hasa) {
                    float2 r = *(const float2*)(add + off);
                    o.x += r.x; o.y += r.y;
                }
                if (Cf) *(float2*)(Cf + off) = o;
                if (Chi) {
                    uint32_t uh, ul;
                    split2(o, uh, ul);
                    *(uint32_t*)(Chi + off) = uh;
                    *(uint32_t*)(Clo + off) = ul;
                }
            }
        }
    }
}

// =============================================================================
// Tensor-core flash attention (mma.sync bf16, split 3-term)
// Block: one (b, h), 64 q rows, 128 threads = 4 warps x 16 q rows.
// 2-stage K/V pipeline; 3 CTAs/SM (regs<=170, smem 3x73.7KB).
// =============================================================================
#define AS    72
#define ATILE (64 * AS * 2)        // 9216 B per 64x64 bf16 tile
#define ASTG  (4 * ATILE)          // kh,kl,vh,vl = 36864 B per stage
#define ATTN_SMEM (2 * ASTG)       // 73728 B

__global__ __launch_bounds__(128, 3)
void attn_mma(const __nv_bfloat16* __restrict__ qh,
              const __nv_bfloat16* __restrict__ ql,
              __nv_bfloat16* __restrict__ oh,
              __nv_bfloat16* __restrict__ ol)
{
    extern __shared__ char smem[];
    const uint32_t sb = smem_u32(smem);
    const int tid  = threadIdx.x;
    const int lane = tid & 31;
    const int wid  = tid >> 5;       // 0..3
    const int b  = blockIdx.z;
    const int h  = blockIdx.y;
    const int qt = blockIdx.x;

    const int grp = lane >> 3;
    const int rA  = (lane & 7) + ((grp & 1) << 3);
    const int cA  = (grp >> 1) << 3;
    const int rB  = (lane & 7) + ((grp >> 1) << 3);
    const int cB  = (grp & 1) << 3;

    const size_t tok0 = (size_t)b * SEQ + (size_t)qt * 64;

    // ---- stage Q tile (64 x 64, hi+lo) into smem, build register frags ----
#pragma unroll
    for (int i = 0; i < 4; i++) {
        int u = tid + i * 128;           // 512 16B units per array
        int r = u >> 3, seg = u & 7;
        const __nv_bfloat16* sh = qh + (tok0 + r) * (3 * CM) + h * HDIM + seg * 8;
        const __nv_bfloat16* sl = ql + (tok0 + r) * (3 * CM) + h * HDIM + seg * 8;
        uint32_t d = (uint32_t)(r * (AS * 2) + seg * 16);
        cpa16(sb + d, sh);
        cpa16(sb + (uint32_t)ATILE + d, sl);
    }
    CPA_COMMIT();
    asm volatile("cp.async.wait_group 0;" ::: "memory");
    __syncthreads();

    uint32_t qfh[4][4], qfl[4][4];
#pragma unroll
    for (int c = 0; c < 4; c++) {
        uint32_t a = sb + (uint32_t)(((wid * 16 + rA) * AS + cA + c * 16) * 2);
        LDMX4(qfh[c], a);
        LDMX4(qfl[c], a + (uint32_t)ATILE);
    }
    __syncthreads();   // Q frags in regs; smem free for K/V pipeline

    float oacc[8][4];
#pragma unroll
    for (int j = 0; j < 8; j++)
#pragma unroll
        for (int q = 0; q < 4; q++) oacc[j][q] = 0.0f;
    float mrow0 = -1e30f, mrow1 = -1e30f, lrow0 = 0.0f, lrow1 = 0.0f;

    // loader: 4 arrays x 64 rows = 256 row-units; 128 threads -> 2 each
    auto load_kv = [&](int kt, int st) {
#pragma unroll
        for (int i = 0; i < 2; i++) {
            const int u = tid + i * 128;
            const int t = u >> 6;          // 0=kh 1=kl 2=vh 3=vl
            const int r = u & 63;
            size_t row = ((size_t)b * SEQ + kt * 64 + r) * (3 * CM) + h * HDIM;
            const __nv_bfloat16* src;
            if      (t == 0) src = qh + row + CM;
            else if (t == 1) src = ql + row + CM;
            else if (t == 2) src = qh + row + 2 * CM;
            else             src = ql + row + 2 * CM;
            uint32_t dst = sb + st * ASTG + t * ATILE + (uint32_t)(r * AS * 2);
#pragma unroll
            for (int s = 0; s < 8; s++) cpa16(dst + s * 16, src + s * 8);
        }
    };

    load_kv(0, 0); CPA_COMMIT();
    load_kv(1, 1); CPA_COMMIT();

    const int NKT = SEQ / 64;   // 32
    for (int kt = 0; kt < NKT; ++kt) {
        if (kt + 1 < NKT) asm volatile("cp.async.wait_group 1;" ::: "memory");
        else              asm volatile("cp.async.wait_group 0;" ::: "memory");
        __syncthreads();

        const uint32_t stb = sb + (kt & 1) * ASTG;

        // ---- S = Q K^T (3-term split), fp32 accum ----
        float sacc[8][4];
#pragma unroll
        for (int j = 0; j < 8; j++)
#pragma unroll
            for (int q = 0; q < 4; q++) sacc[j][q] = 0.0f;

#pragma unroll
        for (int c = 0; c < 4; c++) {
#pragma unroll
            for (int p = 0; p < 4; p++) {
                uint32_t kbh[4], kbl[4];
                uint32_t ka = stb + (uint32_t)(((p * 16 + rB) * AS + cB + c * 16) * 2);
                LDMX4(kbh, ka);
                LDMX4(kbl, ka + ATILE);
#pragma unroll
                for (int q = 0; q < 2; q++) {
                    const int nt = 2 * p + q;
                    mma16816(sacc[nt], qfh[c], kbh[2 * q], kbh[2 * q + 1]);
                    mma16816(sacc[nt], qfh[c], kbl[2 * q], kbl[2 * q + 1]);
                    mma16816(sacc[nt], qfl[c], kbh[2 * q], kbh[2 * q + 1]);
                }
            }
        }

        // ---- online softmax ----
        float mnew0 = mrow0, mnew1 = mrow1;
#pragma unroll
        for (int j = 0; j < 8; j++) {
            sacc[j][0] *= 0.125f; sacc[j][1] *= 0.125f;
            sacc[j][2] *= 0.125f; sacc[j][3] *= 0.125f;
            mnew0 = fmaxf(mnew0, fmaxf(sacc[j][0], sacc[j][1]));
            mnew1 = fmaxf(mnew1, fmaxf(sacc[j][2], sacc[j][3]));
        }
        mnew0 = fmaxf(mnew0, __shfl_xor_sync(0xffffffffu, mnew0, 1));
        mnew0 = fmaxf(mnew0, __shfl_xor_sync(0xffffffffu, mnew0, 2));
        mnew1 = fmaxf(mnew1, __shfl_xor_sync(0xffffffffu, mnew1, 1));
        mnew1 = fmaxf(mnew1, __shfl_xor_sync(0xffffffffu, mnew1, 2));
        const float corr0 = __expf(mrow0 - mnew0);
        const float corr1 = __expf(mrow1 - mnew1);
        mrow0 = mnew0; mrow1 = mnew1;

        uint32_t ph0[8], ph1[8], pl0[8], pl1[8];
        float ts0 = 0.0f, ts1 = 0.0f;
#pragma unroll
        for (int j = 0; j < 8; j++) {
            float p00 = __expf(sacc[j][0] - mnew0);
            float p01 = __expf(sacc[j][1] - mnew0);
            float p10 = __expf(sacc[j][2] - mnew1);
            float p11 = __expf(sacc[j][3] - mnew1);
            ts0 += p00 + p01; ts1 += p10 + p11;
            uint32_t u, ul;
            split2(make_float2(p00, p01), u, ul); ph0[j] = u; pl0[j] = ul;
            split2(make_float2(p10, p11), u, ul); ph1[j] = u; pl1[j] = ul;
        }
        ts0 += __shfl_xor_sync(0xffffffffu, ts0, 1);
        ts0 += __shfl_xor_sync(0xffffffffu, ts0, 2);
        ts1 += __shfl_xor_sync(0xffffffffu, ts1, 1);
        ts1 += __shfl_xor_sync(0xffffffffu, ts1, 2);
        lrow0 = lrow0 * corr0 + ts0;
        lrow1 = lrow1 * corr1 + ts1;
#pragma unroll
        for (int j = 0; j < 8; j++) {
            oacc[j][0] *= corr0; oacc[j][1] *= corr0;
            oacc[j][2] *= corr1; oacc[j][3] *= corr1;
        }

        // ---- O += P V (3-term), V^T via ldmatrix.trans ----
#pragma unroll
        for (int kk = 0; kk < 4; kk++) {
            uint32_t pah[4] = { ph0[2 * kk], ph1[2 * kk], ph0[2 * kk + 1], ph1[2 * kk + 1] };
            uint32_t pal[4] = { pl0[2 * kk], pl1[2 * kk], pl0[2 * kk + 1], pl1[2 * kk + 1] };
#pragma unroll
            for (int p = 0; p < 4; p++) {
                uint32_t vbh[4], vbl[4];
                uint32_t va = stb + 2 * ATILE +
                              (uint32_t)(((kk * 16 + rA) * AS + cA + p * 16) * 2);
                LDMT4(vbh, va);
                LDMT4(vbl, va + ATILE);
#pragma unroll
                for (int q = 0; q < 2; q++) {
                    const int nt = 2 * p + q;
                    mma16816(oacc[nt], pah, vbh[2 * q], vbh[2 * q + 1]);
                    mma16816(oacc[nt], pah, vbl[2 * q], vbl[2 * q + 1]);
                    mma16816(oacc[nt], pal, vbh[2 * q], vbh[2 * q + 1]);
                }
            }
        }

        __syncthreads();
        if (kt + 2 < NKT) { load_kv(kt + 2, kt & 1); CPA_COMMIT(); }
    }

    // ---- finalize: O / l, write bf16 hi/lo at [token][h*64 + d] ----
    const float inv0 = 1.0f / lrow0;
    const float inv1 = 1.0f / lrow1;
    const size_t t0 = tok0 + wid * 16 + (lane >> 2);
    const size_t base0 = t0 * CM + h * HDIM + (lane & 3) * 2;
    const size_t base1 = base0 + (size_t)8 * CM;
#pragma unroll
    for (int j = 0; j < 8; j++) {
        uint32_t uh, ul;
        split2(make_float2(oacc[j][0] * inv0, oacc[j][1] * inv0), uh, ul);
        *(uint32_t*)(oh + base0 + j * 8) = uh;
        *(uint32_t*)(ol + base0 + j * 8) = ul;
        split2(make_float2(oacc[j][2] * inv1, oacc[j][3] * inv1), uh, ul);
        *(uint32_t*)(oh + base1 + j * 8) = uh;
        *(uint32_t*)(ol + base1 + j * 8) = ul;
    }
}

// =============================================================================
// LayerNorm over last dim (1024). One block per row, 256 threads x float4.
// =============================================================================
__global__ __launch_bounds__(256)
void ln_k(const float* __restrict__ in, const float* __restrict__ gamma,
          const float* __restrict__ beta, float* __restrict__ out,
          __nv_bfloat16* __restrict__ ohi, __nv_bfloat16* __restrict__ olo)
{
    const int row = blockIdx.x;
    const int tid = threadIdx.x;
    const float4 v = ((const float4*)(in + (size_t)row * CM))[tid];

    float s  = v.x + v.y + v.z + v.w;
    float ss = v.x * v.x + v.y * v.y + v.z * v.z + v.w * v.w;
#pragma unroll
    for (int o = 16; o > 0; o >>= 1) {
        s  += __shfl_xor_sync(0xffffffffu, s,  o);
        ss += __shfl_xor_sync(0xffffffffu, ss, o);
    }
    __shared__ float rs[8], rq[8];
    if ((tid & 31) == 0) { rs[tid >> 5] = s; rq[tid >> 5] = ss; }
    __syncthreads();
    float tot = 0.0f, totq = 0.0f;
#pragma unroll
    for (int i = 0; i < 8; i++) { tot += rs[i]; totq += rq[i]; }

    const float mean = tot * (1.0f / CM);
    const float var  = totq * (1.0f / CM) - mean * mean;
    const float inv  = rsqrtf(var + 1e-5f);

    const float4 g4 = ((const float4*)gamma)[tid];
    const float4 b4 = ((const float4*)beta)[tid];
    float4 o;
    o.x = (v.x - mean) * inv * g4.x + b4.x;
    o.y = (v.y - mean) * inv * g4.y + b4.y;
    o.z = (v.z - mean) * inv * g4.z + b4.z;
    o.w = (v.w - mean) * inv * g4.w + b4.w;
    ((float4*)(out + (size_t)row * CM))[tid] = o;

    if (ohi) {
        uint32_t u0, l0, u1, l1;
        split2(make_float2(o.x, o.y), u0, l0);
        split2(make_float2(o.z, o.w), u1, l1);
        uint32_t* hp = (uint32_t*)(ohi + (size_t)row * CM + tid * 4);
        uint32_t* lp = (uint32_t*)(olo + (size_t)row * CM + tid * 4);
        hp[0] = u0; hp[1] = u1;
        lp[0] = l0; lp[1] = l1;
    }
}

// =============================================================================
// launch
// =============================================================================
static inline void cvt(const float* x, __nv_bfloat16* hi, __nv_bfloat16* lo, size_t n) {
    int n4 = (int)(n / 4);
    cvt_hilo<<<(n4 + 255) / 256, 256>>>(x, hi, lo, n4);
}

extern "C" void kernel_launch(void* const* d_in, const int* in_sizes, int n_in,
                              void* d_out, int out_size)
{
    (void)in_sizes; (void)n_in; (void)out_size;
    const float* src   = (const float*)d_in[0];
    const float* wqkv  = (const float*)d_in[1];
    const float* wproj = (const float*)d_in[2];
    const float* bproj = (const float*)d_in[3];
    const float* w1    = (const float*)d_in[4];
    const float* b1    = (const float*)d_in[5];
    const float* w2    = (const float*)d_in[6];
    const float* b2    = (const float*)d_in[7];
    const float* g1    = (const float*)d_in[8];
    const float* be1   = (const float*)d_in[9];
    const float* g2    = (const float*)d_in[10];
    const float* be2   = (const float*)d_in[11];
    float* out = (float*)d_out;

    float *qkvf, *res, *x, *fff;
    __nv_bfloat16 *ah, *al, *bh, *bl;
    cudaGetSymbolAddress((void**)&qkvf, g_qkv);
    cudaGetSymbolAddress((void**)&res,  g_res);
    cudaGetSymbolAddress((void**)&x,    g_x);
    cudaGetSymbolAddress((void**)&fff,  g_ff);
    cudaGetSymbolAddress((void**)&ah,   g_ah);
    cudaGetSymbolAddress((void**)&al,   g_al);
    cudaGetSymbolAddress((void**)&bh,   g_bh);
    cudaGetSymbolAddress((void**)&bl,   g_bl);

    __nv_bfloat16* qh  = (__nv_bfloat16*)qkvf;
    __nv_bfloat16* ql  = (__nv_bfloat16*)fff;
    __nv_bfloat16* ffh = (__nv_bfloat16*)qkvf;
    __nv_bfloat16* ffl = (__nv_bfloat16*)fff;

    cudaFuncSetAttribute(gemm_mma<0>, cudaFuncAttributeMaxDynamicSharedMemorySize, GEMM_SMEM);
    cudaFuncSetAttribute(gemm_mma<1>, cudaFuncAttributeMaxDynamicSharedMemorySize, GEMM_SMEM);
    cudaFuncSetAttribute(attn_mma,    cudaFuncAttributeMaxDynamicSharedMemorySize, ATTN_SMEM);

    // 1) QKV projection -> bf16 hi/lo directly
    cvt(src,  ah, al, (size_t)MTOT * CM);
    cvt(wqkv, bh, bl, (size_t)3 * CM * CM);
    gemm_mma<0><<<dim3(3 * CM / 256, MTOT / 128), 256, GEMM_SMEM>>>(
        ah, al, bh, bl, nullptr, nullptr, nullptr, qh, ql, MTOT, 3 * CM, CM);

    // 2) flash attention -> bf16 hi/lo attn output
    attn_mma<<<dim3(SEQ / 64, NHEAD, NB), 128, ATTN_SMEM>>>(qh, ql, ah, al);

    // 3) output projection + bias + residual(src) -> fp32 res
    cvt(wproj, bh, bl, (size_t)CM * CM);
    gemm_mma<0><<<dim3(CM / 256, MTOT / 128), 256, GEMM_SMEM>>>(
        ah, al, bh, bl, bproj, src, res, nullptr, nullptr, MTOT, CM, CM);

    // 4) LayerNorm 1 -> fp32 x + bf16 hi/lo
    ln_k<<<MTOT, 256>>>(res, g1, be1, x, ah, al);

    // 5) FFN up: relu(x @ w1^T + b1) -> bf16 hi/lo directly
    cvt(w1, bh, bl, (size_t)FF * CM);
    gemm_mma<1><<<dim3(FF / 256, MTOT / 128), 256, GEMM_SMEM>>>(
        ah, al, bh, bl, b1, nullptr, nullptr, ffh, ffl, MTOT, FF, CM);

    // 6) FFN down + bias + residual(x) -> fp32 res
    cvt(w2, bh, bl, (size_t)CM * FF);
    gemm_mma<0><<<dim3(CM / 256, MTOT / 128), 256, GEMM_SMEM>>>(
        ffh, ffl, bh, bl, b2, x, res, nullptr, nullptr, MTOT, CM, FF);

    // 7) LayerNorm 2 -> output
    ln_k<<<MTOT, 256>>>(res, g2, be2, out, nullptr, nullptr);
}